// round 14
// baseline (speedup 1.0000x reference)
#include <cuda_runtime.h>

#define NN 50000
#define EE 800000
#define FIN 128
#define HH 64
#define HX 128   // 2H

#define MSG_EPS 1e-7f
#define SCAN_NBLK ((NN + 255) / 256)   // 196
#define EDGE_BLOCKS ((EE + 255) / 256) // 3125
#define NWT (NN / 16)                  // 3125 warp-tiles (exact)

// ---------------- device scratch (no allocation allowed) ----------------
__device__ int   g_srcSorted[EE];
__device__ int   g_rank[EE];           // edge's arrival rank within its dst
__device__ int   g_cnt[NN];            // 0 at run start (zeroed at run end)
__device__ int   g_off[NN + 1];
__device__ volatile unsigned long long g_state[SCAN_NBLK];  // 0 at run start
__device__ float g_xenc[NN * HH];
__device__ float g_tmp[NN * HH];
__device__ float g_x1[NN * HH];

// ---------------- tf32 mma helpers ----------------
__device__ __forceinline__ unsigned f2tf(float f) {
    unsigned r;
    asm("cvt.rna.tf32.f32 %0, %1;" : "=r"(r) : "f"(f));
    return r;
}
__device__ __forceinline__ float ex2f(float x) {
    float r;
    asm("ex2.approx.ftz.f32 %0, %1;" : "=f"(r) : "f"(x));
    return r;
}
__device__ __forceinline__ void mma8(float& d0, float& d1, float& d2, float& d3,
                                     unsigned a0, unsigned a1, unsigned a2, unsigned a3,
                                     unsigned b0, unsigned b1) {
    asm("mma.sync.aligned.m16n8k8.row.col.f32.tf32.tf32.f32 "
        "{%0,%1,%2,%3},{%4,%5,%6,%7},{%8,%9},{%0,%1,%2,%3};"
        : "+f"(d0), "+f"(d1), "+f"(d2), "+f"(d3)
        : "r"(a0), "r"(a1), "r"(a2), "r"(a3), "r"(b0), "r"(b1));
}

// -------- inline dtype detect helper --------
__device__ __forceinline__ int detect_is64(const int* __restrict__ ei32,
                                           int t, int* s_flag) {
    int v = ei32[2 * (t & 127) + 1];
    int any = __syncthreads_or(v != 0);
    if (t == 0) *s_flag = !any;
    __syncthreads();
    return *s_flag;
}
__device__ __forceinline__ void decode_edge(const int* __restrict__ ei32,
                                            int is64, int e, int* s, int* d) {
    if (is64) {
        const long long* p = (const long long*)ei32;
        *s = (int)p[e];
        *d = (int)p[EE + e];
    } else {
        *s = ei32[e];
        *d = ei32[EE + e];
    }
}

// ---------------- count degrees (records rank) ----------------
__global__ void count_kernel(const int* __restrict__ ei32) {
    __shared__ int s_is64;
    int t = threadIdx.x;
    int is64 = detect_is64(ei32, t, &s_is64);
    int e = blockIdx.x * 256 + t;
    if (e >= EE) return;
    int s, d;
    decode_edge(ei32, is64, e, &s, &d);
    g_rank[e] = atomicAdd(&g_cnt[d], 1);
}

// ------- warp-autonomous encoder GEMM: x[N,128] @ W[128,64] + b ----------
#define WSE 72    // Ws stride (64-wide +8 pad)
__global__ void __launch_bounds__(128) encoder_kernel(
    const float* __restrict__ x, const float* __restrict__ W,
    const float* __restrict__ b) {
    __shared__ unsigned Ws[128 * WSE];
    __shared__ float    Xs[4][16 * 132];
    __shared__ float    bs[64];
    int tid = threadIdx.x;
    int lane = tid & 31, w = tid >> 5;
    int g = lane >> 2, t = lane & 3;

    for (int i = tid; i < 128 * 64; i += 128)
        Ws[(i >> 6) * WSE + (i & 63)] = f2tf(W[i]);
    if (tid < 64) bs[tid] = b[tid];
    __syncthreads();

    float* Xsw = Xs[w];
    for (int tile = blockIdx.x * 4 + w; tile < NWT; tile += gridDim.x * 4) {
        int r0 = tile * 16;
        __syncwarp();
        const float4* X4 = (const float4*)(x + (size_t)r0 * FIN);
        float4* S4 = (float4*)Xsw;
#pragma unroll
        for (int i = 0; i < 16; i++) {
            int idx = lane + i * 32;
            int r = idx >> 5, c4 = idx & 31;
            float4 v = X4[r * 32 + c4];
            float4 o;
            o.x = __uint_as_float(f2tf(v.x));
            o.y = __uint_as_float(f2tf(v.y));
            o.z = __uint_as_float(f2tf(v.z));
            o.w = __uint_as_float(f2tf(v.w));
            S4[r * 33 + c4] = o;
        }
        __syncwarp();

        float acc[8][4];
#pragma unroll
        for (int i = 0; i < 8; i++) {
            acc[i][0] = 0.f; acc[i][1] = 0.f; acc[i][2] = 0.f; acc[i][3] = 0.f;
        }
#pragma unroll
        for (int ks = 0; ks < 16; ks++) {
            int k0 = ks * 8;
            unsigned a0 = __float_as_uint(Xsw[g * 132 + k0 + t]);
            unsigned a1 = __float_as_uint(Xsw[(g + 8) * 132 + k0 + t]);
            unsigned a2 = __float_as_uint(Xsw[g * 132 + k0 + t + 4]);
            unsigned a3 = __float_as_uint(Xsw[(g + 8) * 132 + k0 + t + 4]);
#pragma unroll
            for (int nt = 0; nt < 8; nt++) {
                unsigned b0 = Ws[(k0 + t) * WSE + nt * 8 + g];
                unsigned b1f = Ws[(k0 + t + 4) * WSE + nt * 8 + g];
                mma8(acc[nt][0], acc[nt][1], acc[nt][2], acc[nt][3],
                     a0, a1, a2, a3, b0, b1f);
            }
        }
#pragma unroll
        for (int nt = 0; nt < 8; nt++) {
            int col = nt * 8 + 2 * t;
            float2 bb = *(float2*)&bs[col];
            *(float2*)&g_xenc[(size_t)(r0 + g) * HH + col] =
                make_float2(acc[nt][0] + bb.x, acc[nt][1] + bb.y);
            *(float2*)&g_xenc[(size_t)(r0 + g + 8) * HH + col] =
                make_float2(acc[nt][2] + bb.x, acc[nt][3] + bb.y);
        }
    }
}

// ---- block exclusive scan helper ----
__device__ __forceinline__ int block_excl_scan_256(int v, int* wsum, int t) {
    int lane = t & 31;
    int w = t >> 5;
    int incl = v;
#pragma unroll
    for (int o = 1; o < 32; o <<= 1) {
        int n = __shfl_up_sync(0xffffffffu, incl, o);
        if (lane >= o) incl += n;
    }
    if (lane == 31) wsum[w] = incl;
    __syncthreads();
    if (t == 0) {
        int run = 0;
#pragma unroll
        for (int i = 0; i < 8; i++) { int c = wsum[i]; wsum[i] = run; run += c; }
        wsum[8] = run;
    }
    __syncthreads();
    return incl - v + wsum[w];
}

// ---- single-pass decoupled-lookback scan: g_cnt -> g_off ----
__global__ void scan_lb_kernel() {
    __shared__ int wsum[9];
    __shared__ int s_excl;
    int b = blockIdx.x, t = threadIdx.x;
    int idx = b * 256 + t;
    int v = (idx < NN) ? g_cnt[idx] : 0;
    int excl = block_excl_scan_256(v, wsum, t);
    int total = wsum[8];

    if (t == 0) {
        unsigned long long st = (b == 0)
            ? ((2ULL << 32) | (unsigned)total)
            : ((1ULL << 32) | (unsigned)total);
        atomicExch((unsigned long long*)&g_state[b], st);
        if (b == 0) s_excl = 0;
    }
    if (b > 0 && t < 32) {
        int lane = t;
        int look = b - 1;
        int run = 0;
        while (true) {
            int ip = look - lane;
            unsigned long long s;
            if (ip >= 0) {
                do { s = g_state[ip]; } while ((s >> 32) == 0);
            } else {
                s = (2ULL << 32);
            }
            int isPref = ((s >> 32) == 2u);
            unsigned mask = __ballot_sync(0xffffffffu, isPref);
            int val = (int)(s & 0xffffffffu);
            if (mask) {
                int p = __ffs(mask) - 1;
                int contrib = (lane <= p) ? val : 0;
#pragma unroll
                for (int o = 16; o; o >>= 1) contrib += __shfl_xor_sync(0xffffffffu, contrib, o);
                run += contrib;
                break;
            } else {
                int contrib = val;
#pragma unroll
                for (int o = 16; o; o >>= 1) contrib += __shfl_xor_sync(0xffffffffu, contrib, o);
                run += contrib;
                look -= 32;
            }
        }
        if (lane == 0) {
            s_excl = run;
            atomicExch((unsigned long long*)&g_state[b],
                       (2ULL << 32) | (unsigned)(run + total));
        }
    }
    __syncthreads();
    int base = s_excl;
    if (idx < NN) g_off[idx] = excl + base;
    if (b == SCAN_NBLK - 1 && t == 0) g_off[NN] = EE;
}

// ---------------- scatter (no atomics: uses recorded rank) ----------------
__global__ void scatter_kernel(const int* __restrict__ ei32) {
    __shared__ int s_is64;
    int t = threadIdx.x;
    int is64 = detect_is64(ei32, t, &s_is64);
    int e = blockIdx.x * blockDim.x + t;
    if (e >= EE) return;
    int s, d;
    decode_edge(ei32, is64, e, &s, &d);
    g_srcSorted[g_off[d] + g_rank[e]] = s;
}

// ---------------- softmax aggregation ----------------
// Warp per dst node; half-warp (16 lanes x float4 = 64 ch) per edge.
// 4 edges in flight per half-warp (8 per warp) to reach the LTS cap.
__global__ void agg_kernel(int sel, const float* __restrict__ tptr) {
    const float4* __restrict__ xin4 = (const float4*)(sel ? g_x1 : g_xenc);
    int gw = (blockIdx.x * blockDim.x + threadIdx.x) >> 5;
    int lane = threadIdx.x & 31;
    if (gw >= NN) return;
    int half = lane >> 4;
    int li = lane & 15;
    float t2 = (*tptr) * 1.44269504f;
    int e0 = g_off[gw], e1 = g_off[gw + 1];

    float S0 = 0.f, S1 = 0.f, S2 = 0.f, S3 = 0.f;
    float A0 = 0.f, A1 = 0.f, A2 = 0.f, A3 = 0.f;

    int e = e0 + half;
    // 4 edges per half-warp per iteration (8 per warp): 4 LDG.128 in flight
    for (; e + 6 < e1; e += 8) {
        int sA = g_srcSorted[e];
        int sB = g_srcSorted[e + 2];
        int sC = g_srcSorted[e + 4];
        int sD = g_srcSorted[e + 6];
        float4 vA = xin4[sA * 16 + li];
        float4 vB = xin4[sB * 16 + li];
        float4 vC = xin4[sC * 16 + li];
        float4 vD = xin4[sD * 16 + li];
        float r, ex;
        r = fmaxf(vA.x, 0.f); ex = ex2f(r * t2); S0 += ex; A0 += r * ex;
        r = fmaxf(vA.y, 0.f); ex = ex2f(r * t2); S1 += ex; A1 += r * ex;
        r = fmaxf(vA.z, 0.f); ex = ex2f(r * t2); S2 += ex; A2 += r * ex;
        r = fmaxf(vA.w, 0.f); ex = ex2f(r * t2); S3 += ex; A3 += r * ex;
        r = fmaxf(vB.x, 0.f); ex = ex2f(r * t2); S0 += ex; A0 += r * ex;
        r = fmaxf(vB.y, 0.f); ex = ex2f(r * t2); S1 += ex; A1 += r * ex;
        r = fmaxf(vB.z, 0.f); ex = ex2f(r * t2); S2 += ex; A2 += r * ex;
        r = fmaxf(vB.w, 0.f); ex = ex2f(r * t2); S3 += ex; A3 += r * ex;
        r = fmaxf(vC.x, 0.f); ex = ex2f(r * t2); S0 += ex; A0 += r * ex;
        r = fmaxf(vC.y, 0.f); ex = ex2f(r * t2); S1 += ex; A1 += r * ex;
        r = fmaxf(vC.z, 0.f); ex = ex2f(r * t2); S2 += ex; A2 += r * ex;
        r = fmaxf(vC.w, 0.f); ex = ex2f(r * t2); S3 += ex; A3 += r * ex;
        r = fmaxf(vD.x, 0.f); ex = ex2f(r * t2); S0 += ex; A0 += r * ex;
        r = fmaxf(vD.y, 0.f); ex = ex2f(r * t2); S1 += ex; A1 += r * ex;
        r = fmaxf(vD.z, 0.f); ex = ex2f(r * t2); S2 += ex; A2 += r * ex;
        r = fmaxf(vD.w, 0.f); ex = ex2f(r * t2); S3 += ex; A3 += r * ex;
    }
    // 2-edge step remainder
    for (; e + 2 < e1; e += 4) {
        int sA = g_srcSorted[e];
        int sB = g_srcSorted[e + 2];
        float4 vA = xin4[sA * 16 + li];
        float4 vB = xin4[sB * 16 + li];
        float r, ex;
        r = fmaxf(vA.x, 0.f); ex = ex2f(r * t2); S0 += ex; A0 += r * ex;
        r = fmaxf(vA.y, 0.f); ex = ex2f(r * t2); S1 += ex; A1 += r * ex;
        r = fmaxf(vA.z, 0.f); ex = ex2f(r * t2); S2 += ex; A2 += r * ex;
        r = fmaxf(vA.w, 0.f); ex = ex2f(r * t2); S3 += ex; A3 += r * ex;
        r = fmaxf(vB.x, 0.f); ex = ex2f(r * t2); S0 += ex; A0 += r * ex;
        r = fmaxf(vB.y, 0.f); ex = ex2f(r * t2); S1 += ex; A1 += r * ex;
        r = fmaxf(vB.z, 0.f); ex = ex2f(r * t2); S2 += ex; A2 += r * ex;
        r = fmaxf(vB.w, 0.f); ex = ex2f(r * t2); S3 += ex; A3 += r * ex;
    }
    if (e < e1) {
        int sA = g_srcSorted[e];
        float4 vA = xin4[sA * 16 + li];
        float r, ex;
        r = fmaxf(vA.x, 0.f); ex = ex2f(r * t2); S0 += ex; A0 += r * ex;
        r = fmaxf(vA.y, 0.f); ex = ex2f(r * t2); S1 += ex; A1 += r * ex;
        r = fmaxf(vA.z, 0.f); ex = ex2f(r * t2); S2 += ex; A2 += r * ex;
        r = fmaxf(vA.w, 0.f); ex = ex2f(r * t2); S3 += ex; A3 += r * ex;
    }
    S0 += __shfl_xor_sync(0xffffffffu, S0, 16);
    S1 += __shfl_xor_sync(0xffffffffu, S1, 16);
    S2 += __shfl_xor_sync(0xffffffffu, S2, 16);
    S3 += __shfl_xor_sync(0xffffffffu, S3, 16);
    A0 += __shfl_xor_sync(0xffffffffu, A0, 16);
    A1 += __shfl_xor_sync(0xffffffffu, A1, 16);
    A2 += __shfl_xor_sync(0xffffffffu, A2, 16);
    A3 += __shfl_xor_sync(0xffffffffu, A3, 16);

    if (half == 0) {
        float4 self = xin4[gw * 16 + li];
        float4 o;
        o.x = A0 / (S0 + 1e-16f) + MSG_EPS + self.x;
        o.y = A1 / (S1 + 1e-16f) + MSG_EPS + self.y;
        o.z = A2 / (S2 + 1e-16f) + MSG_EPS + self.z;
        o.w = A3 / (S3 + 1e-16f) + MSG_EPS + self.w;
        ((float4*)g_tmp)[gw * 16 + li] = o;
    }
}

// -------- warp-autonomous fused MLP via tf32 mma --------
#define W1S 136   // 128-wide +8 pad
#define W2S 72    // 64-wide +8 pad
template <int FINAL>
__global__ void __launch_bounds__(128) mlp_kernel(
    const float* __restrict__ W1, const float* __restrict__ b1,
    const float* __restrict__ g1, const float* __restrict__ be1,
    const float* __restrict__ W2, const float* __restrict__ b2,
    const float* __restrict__ ln1g, const float* __restrict__ ln1b,
    const float* __restrict__ ng, const float* __restrict__ nb,
    const float* __restrict__ lw, const float* __restrict__ lb,
    float* __restrict__ out) {
    __shared__ unsigned W1s[64 * W1S];
    __shared__ unsigned W2s[128 * W2S];
    __shared__ float    Xs[4][16 * 68];
    __shared__ float    b1s[128], g1s[128], be1s[128], b2s[64];
    __shared__ float    l1gs[64], l1bs[64], ngs[128], nbs[128], lws[128];

    int tid = threadIdx.x;
    int lane = tid & 31, w = tid >> 5;
    int g = lane >> 2, t = lane & 3;

    for (int i = tid; i < 64 * 128; i += 128)
        W1s[(i >> 7) * W1S + (i & 127)] = f2tf(W1[i]);
    for (int i = tid; i < 128 * 64; i += 128)
        W2s[(i >> 6) * W2S + (i & 63)] = f2tf(W2[i]);
    b1s[tid] = b1[tid]; g1s[tid] = g1[tid]; be1s[tid] = be1[tid];
    if (tid < 64) b2s[tid] = b2[tid];
    if (FINAL) {
        if (tid < 64) { l1gs[tid] = ln1g[tid]; l1bs[tid] = ln1b[tid]; }
        ngs[tid] = ng[tid]; nbs[tid] = nb[tid]; lws[tid] = lw[tid];
    }
    __syncthreads();

    float lbv = FINAL ? lb[0] : 0.f;
    float* Xsw = Xs[w];
    int srcA = (lane & ~3) | (t >> 1);
    int srcB = srcA + 2;
    bool odd = (t & 1) != 0;

    for (int tile = blockIdx.x * 4 + w; tile < NWT; tile += gridDim.x * 4) {
        int r0 = tile * 16;

        __syncwarp();
        const float4* X4 = (const float4*)(g_tmp + (size_t)r0 * HH);
        float4* S4 = (float4*)Xsw;
#pragma unroll
        for (int i = 0; i < 8; i++) {
            int idx = lane + i * 32;
            int r = idx >> 4, c4 = idx & 15;
            float4 v = X4[r * 16 + c4];
            float4 o;
            o.x = __uint_as_float(f2tf(v.x));
            o.y = __uint_as_float(f2tf(v.y));
            o.z = __uint_as_float(f2tf(v.z));
            o.w = __uint_as_float(f2tf(v.w));
            S4[r * 17 + c4] = o;
        }
        __syncwarp();

        float acc[16][4];
#pragma unroll
        for (int i = 0; i < 16; i++) {
            acc[i][0] = 0.f; acc[i][1] = 0.f; acc[i][2] = 0.f; acc[i][3] = 0.f;
        }
#pragma unroll
        for (int ks = 0; ks < 8; ks++) {
            int k0 = ks * 8;
            unsigned a0 = __float_as_uint(Xsw[g * 68 + k0 + t]);
            unsigned a1 = __float_as_uint(Xsw[(g + 8) * 68 + k0 + t]);
            unsigned a2 = __float_as_uint(Xsw[g * 68 + k0 + t + 4]);
            unsigned a3 = __float_as_uint(Xsw[(g + 8) * 68 + k0 + t + 4]);
#pragma unroll
            for (int nt = 0; nt < 16; nt++) {
                unsigned b0 = W1s[(k0 + t) * W1S + nt * 8 + g];
                unsigned b1f = W1s[(k0 + t + 4) * W1S + nt * 8 + g];
                mma8(acc[nt][0], acc[nt][1], acc[nt][2], acc[nt][3],
                     a0, a1, a2, a3, b0, b1f);
            }
        }

        float sg = 0.f, qg = 0.f, sh = 0.f, qh = 0.f;
#pragma unroll
        for (int nt = 0; nt < 16; nt++) {
            float2 bb = *(float2*)&b1s[nt * 8 + 2 * t];
            acc[nt][0] += bb.x; acc[nt][1] += bb.y;
            acc[nt][2] += bb.x; acc[nt][3] += bb.y;
            sg += acc[nt][0] + acc[nt][1];
            qg += acc[nt][0] * acc[nt][0] + acc[nt][1] * acc[nt][1];
            sh += acc[nt][2] + acc[nt][3];
            qh += acc[nt][2] * acc[nt][2] + acc[nt][3] * acc[nt][3];
        }
        sg += __shfl_xor_sync(~0u, sg, 1); sg += __shfl_xor_sync(~0u, sg, 2);
        qg += __shfl_xor_sync(~0u, qg, 1); qg += __shfl_xor_sync(~0u, qg, 2);
        sh += __shfl_xor_sync(~0u, sh, 1); sh += __shfl_xor_sync(~0u, sh, 2);
        qh += __shfl_xor_sync(~0u, qh, 1); qh += __shfl_xor_sync(~0u, qh, 2);
        float mug = sg * (1.f / HX), muh = sh * (1.f / HX);
        float rg = rsqrtf(qg * (1.f / HX) - mug * mug + 1e-5f);
        float rh = rsqrtf(qh * (1.f / HX) - muh * muh + 1e-5f);
#pragma unroll
        for (int nt = 0; nt < 16; nt++) {
            float2 gg = *(float2*)&g1s[nt * 8 + 2 * t];
            float2 be = *(float2*)&be1s[nt * 8 + 2 * t];
            acc[nt][0] = __uint_as_float(f2tf(fmaxf((acc[nt][0] - mug) * rg * gg.x + be.x, 0.f)));
            acc[nt][1] = __uint_as_float(f2tf(fmaxf((acc[nt][1] - mug) * rg * gg.y + be.y, 0.f)));
            acc[nt][2] = __uint_as_float(f2tf(fmaxf((acc[nt][2] - muh) * rh * gg.x + be.x, 0.f)));
            acc[nt][3] = __uint_as_float(f2tf(fmaxf((acc[nt][3] - muh) * rh * gg.y + be.y, 0.f)));
        }

        float acc2[8][4];
#pragma unroll
        for (int i = 0; i < 8; i++) {
            acc2[i][0] = 0.f; acc2[i][1] = 0.f; acc2[i][2] = 0.f; acc2[i][3] = 0.f;
        }
#pragma unroll
        for (int ks = 0; ks < 16; ks++) {
            int k0 = ks * 8;
            float x0 = __shfl_sync(~0u, acc[ks][0], srcA);
            float x1v = __shfl_sync(~0u, acc[ks][1], srcA);
            float y0 = __shfl_sync(~0u, acc[ks][0], srcB);
            float y1 = __shfl_sync(~0u, acc[ks][1], srcB);
            float z0 = __shfl_sync(~0u, acc[ks][2], srcA);
            float z1 = __shfl_sync(~0u, acc[ks][3], srcA);
            float u0 = __shfl_sync(~0u, acc[ks][2], srcB);
            float u1 = __shfl_sync(~0u, acc[ks][3], srcB);
            unsigned a0 = __float_as_uint(odd ? x1v : x0);
            unsigned a1 = __float_as_uint(odd ? z1 : z0);
            unsigned a2 = __float_as_uint(odd ? y1 : y0);
            unsigned a3 = __float_as_uint(odd ? u1 : u0);
#pragma unroll
            for (int nt = 0; nt < 8; nt++) {
                unsigned b0 = W2s[(k0 + t) * W2S + nt * 8 + g];
                unsigned b1f = W2s[(k0 + t + 4) * W2S + nt * 8 + g];
                mma8(acc2[nt][0], acc2[nt][1], acc2[nt][2], acc2[nt][3],
                     a0, a1, a2, a3, b0, b1f);
            }
        }

        if (!FINAL) {
#pragma unroll
            for (int nt = 0; nt < 8; nt++) {
                float2 bb = *(float2*)&b2s[nt * 8 + 2 * t];
                int col = nt * 8 + 2 * t;
                *(float2*)&g_x1[(size_t)(r0 + g) * HH + col] =
                    make_float2(acc2[nt][0] + bb.x, acc2[nt][1] + bb.y);
                *(float2*)&g_x1[(size_t)(r0 + g + 8) * HH + col] =
                    make_float2(acc2[nt][2] + bb.x, acc2[nt][3] + bb.y);
            }
        } else {
            float hsg = 0.f, hqg = 0.f, hsh = 0.f, hqh = 0.f;
#pragma unroll
            for (int nt = 0; nt < 8; nt++) {
                float2 bb = *(float2*)&b2s[nt * 8 + 2 * t];
                acc2[nt][0] += bb.x; acc2[nt][1] += bb.y;
                acc2[nt][2] += bb.x; acc2[nt][3] += bb.y;
                hsg += acc2[nt][0] + acc2[nt][1];
                hqg += acc2[nt][0] * acc2[nt][0] + acc2[nt][1] * acc2[nt][1];
                hsh += acc2[nt][2] + acc2[nt][3];
                hqh += acc2[nt][2] * acc2[nt][2] + acc2[nt][3] * acc2[nt][3];
            }
            hsg += __shfl_xor_sync(~0u, hsg, 1); hsg += __shfl_xor_sync(~0u, hsg, 2);
            hqg += __shfl_xor_sync(~0u, hqg, 1); hqg += __shfl_xor_sync(~0u, hqg, 2);
            hsh += __shfl_xor_sync(~0u, hsh, 1); hsh += __shfl_xor_sync(~0u, hsh, 2);
            hqh += __shfl_xor_sync(~0u, hqh, 1); hqh += __shfl_xor_sync(~0u, hqh, 2);
            float mu1g = hsg * (1.f / 64.f), mu1h = hsh * (1.f / 64.f);
            float r1g = rsqrtf(hqg * (1.f / 64.f) - mu1g * mu1g + 1e-5f);
            float r1h = rsqrtf(hqh * (1.f / 64.f) - mu1h * mu1h + 1e-5f);

            float hng[8][2], hnh[8][2];
            float2 xg[8], xh[8];
            float s2g = 0.f, q2g = 0.f, s2h = 0.f, q2h = 0.f;
#pragma unroll
            for (int nt = 0; nt < 8; nt++) {
                int col = nt * 8 + 2 * t;
                float2 lg = *(float2*)&l1gs[col];
                float2 lbb = *(float2*)&l1bs[col];
                hng[nt][0] = fmaxf((acc2[nt][0] - mu1g) * r1g * lg.x + lbb.x, 0.f);
                hng[nt][1] = fmaxf((acc2[nt][1] - mu1g) * r1g * lg.y + lbb.y, 0.f);
                hnh[nt][0] = fmaxf((acc2[nt][2] - mu1h) * r1h * lg.x + lbb.x, 0.f);
                hnh[nt][1] = fmaxf((acc2[nt][3] - mu1h) * r1h * lg.y + lbb.y, 0.f);
                xg[nt] = *(const float2*)&g_x1[(size_t)(r0 + g) * HH + col];
                xh[nt] = *(const float2*)&g_x1[(size_t)(r0 + g + 8) * HH + col];
                s2g += xg[nt].x + xg[nt].y + hng[nt][0] + hng[nt][1];
                q2g += xg[nt].x * xg[nt].x + xg[nt].y * xg[nt].y
                     + hng[nt][0] * hng[nt][0] + hng[nt][1] * hng[nt][1];
                s2h += xh[nt].x + xh[nt].y + hnh[nt][0] + hnh[nt][1];
                q2h += xh[nt].x * xh[nt].x + xh[nt].y * xh[nt].y
                     + hnh[nt][0] * hnh[nt][0] + hnh[nt][1] * hnh[nt][1];
            }
            s2g += __shfl_xor_sync(~0u, s2g, 1); s2g += __shfl_xor_sync(~0u, s2g, 2);
            q2g += __shfl_xor_sync(~0u, q2g, 1); q2g += __shfl_xor_sync(~0u, q2g, 2);
            s2h += __shfl_xor_sync(~0u, s2h, 1); s2h += __shfl_xor_sync(~0u, s2h, 2);
            q2h += __shfl_xor_sync(~0u, q2h, 1); q2h += __shfl_xor_sync(~0u, q2h, 2);
            float mu2g = s2g * (1.f / 128.f), mu2h = s2h * (1.f / 128.f);
            float r2g = rsqrtf(q2g * (1.f / 128.f) - mu2g * mu2g + 1e-5f);
            float r2h = rsqrtf(q2h * (1.f / 128.f) - mu2h * mu2h + 1e-5f);

            float dg = 0.f, dh = 0.f;
#pragma unroll
            for (int nt = 0; nt < 8; nt++) {
                int col = nt * 8 + 2 * t;
                float2 ngx = *(float2*)&ngs[col];
                float2 nbx = *(float2*)&nbs[col];
                float2 ngh2 = *(float2*)&ngs[64 + col];
                float2 nbh2 = *(float2*)&nbs[64 + col];
                float2 lwx = *(float2*)&lws[col];
                float2 lwh2 = *(float2*)&lws[64 + col];
                dg += fmaxf((xg[nt].x - mu2g) * r2g * ngx.x + nbx.x, 0.f) * lwx.x
                    + fmaxf((xg[nt].y - mu2g) * r2g * ngx.y + nbx.y, 0.f) * lwx.y
                    + fmaxf((hng[nt][0] - mu2g) * r2g * ngh2.x + nbh2.x, 0.f) * lwh2.x
                    + fmaxf((hng[nt][1] - mu2g) * r2g * ngh2.y + nbh2.y, 0.f) * lwh2.y;
                dh += fmaxf((xh[nt].x - mu2h) * r2h * ngx.x + nbx.x, 0.f) * lwx.x
                    + fmaxf((xh[nt].y - mu2h) * r2h * ngx.y + nbx.y, 0.f) * lwx.y
                    + fmaxf((hnh[nt][0] - mu2h) * r2h * ngh2.x + nbh2.x, 0.f) * lwh2.x
                    + fmaxf((hnh[nt][1] - mu2h) * r2h * ngh2.y + nbh2.y, 0.f) * lwh2.y;
            }
            dg += __shfl_xor_sync(~0u, dg, 1); dg += __shfl_xor_sync(~0u, dg, 2);
            dh += __shfl_xor_sync(~0u, dh, 1); dh += __shfl_xor_sync(~0u, dh, 2);
            if (t == 0) {
                out[r0 + g] = dg + lbv;
                out[r0 + g + 8] = dh + lbv;
            }
        }
    }

    if (FINAL) {
        for (int i = blockIdx.x * blockDim.x + tid; i < NN; i += gridDim.x * blockDim.x)
            g_cnt[i] = 0;
        int i = blockIdx.x * blockDim.x + tid;
        if (i < SCAN_NBLK) *((unsigned long long*)&g_state[i]) = 0ULL;
    }
}

// ---------------- launch ----------------
extern "C" void kernel_launch(void* const* d_in, const int* in_sizes, int n_in,
                              void* d_out, int out_size) {
    const float* x    = (const float*)d_in[0];
    const void*  ei   = d_in[1];
    const float* encW = (const float*)d_in[2];
    const float* encB = (const float*)d_in[3];
    const float* t    = (const float*)d_in[4];
    const float* W1   = (const float*)d_in[5];
    const float* b1   = (const float*)d_in[6];
    const float* g1   = (const float*)d_in[7];
    const float* be1  = (const float*)d_in[8];
    const float* W2   = (const float*)d_in[9];
    const float* b2   = (const float*)d_in[10];
    const float* ln1g = (const float*)d_in[11];
    const float* ln1b = (const float*)d_in[12];
    const float* ng   = (const float*)d_in[13];
    const float* nb   = (const float*)d_in[14];
    const float* lw   = (const float*)d_in[15];
    const float* lb   = (const float*)d_in[16];
    float* out = (float*)d_out;

    const int AGG_BLOCKS = (NN * 32 + 255) / 256;

    cudaStream_t sB;
    cudaEvent_t evF, evJ;
    cudaStreamCreateWithFlags(&sB, cudaStreamNonBlocking);
    cudaEventCreateWithFlags(&evF, cudaEventDisableTiming);
    cudaEventCreateWithFlags(&evJ, cudaEventDisableTiming);

    // fork: encoder runs on sB, concurrent with the CSR chain
    cudaEventRecord(evF, 0);
    cudaStreamWaitEvent(sB, evF, 0);
    encoder_kernel<<<296, 128, 0, sB>>>(x, encW, encB);
    cudaEventRecord(evJ, sB);

    count_kernel<<<EDGE_BLOCKS, 256>>>((const int*)ei);
    scan_lb_kernel<<<SCAN_NBLK, 256>>>();
    scatter_kernel<<<EDGE_BLOCKS, 256>>>((const int*)ei);

    // join: agg1 needs both scatter (stream 0) and encoder (sB)
    cudaStreamWaitEvent(0, evJ, 0);
    agg_kernel<<<AGG_BLOCKS, 256>>>(0, t);
    mlp_kernel<0><<<296, 128>>>(W1, b1, g1, be1, W2, b2,
                                ln1g, ln1b, ng, nb, lw, lb, out);
    agg_kernel<<<AGG_BLOCKS, 256>>>(1, t);
    mlp_kernel<1><<<296, 128>>>(W1, b1, g1, be1, W2, b2,
                                ln1g, ln1b, ng, nb, lw, lb, out);
}

// round 15
// speedup vs baseline: 1.0007x; 1.0007x over previous
#include <cuda_runtime.h>

#define NN 50000
#define EE 800000
#define FIN 128
#define HH 64
#define HX 128   // 2H

#define MSG_EPS 1e-7f
#define SCAN_NBLK ((NN + 255) / 256)    // 196
#define CNT_BLOCKS ((EE + 255) / 256)   // 3125
#define SCAT_BLOCKS ((EE + 1023) / 1024) // 782 (4 edges/thread)
#define NWT (NN / 16)                   // 3125 warp-tiles (exact)

// ---------------- device scratch (no allocation allowed) ----------------
__device__ int   g_srcSorted[EE];
__device__ int   g_rank[EE];           // edge's arrival rank within its dst
__device__ int   g_cnt[NN];            // 0 at run start (zeroed at run end)
__device__ int   g_off[NN + 1];
__device__ volatile unsigned long long g_state[SCAN_NBLK];  // 0 at run start
__device__ float g_xenc[NN * HH];
__device__ float g_tmp[NN * HH];
__device__ float g_x1[NN * HH];

// ---------------- tf32 mma helpers ----------------
__device__ __forceinline__ unsigned f2tf(float f) {
    unsigned r;
    asm("cvt.rna.tf32.f32 %0, %1;" : "=r"(r) : "f"(f));
    return r;
}
__device__ __forceinline__ float ex2f(float x) {
    float r;
    asm("ex2.approx.ftz.f32 %0, %1;" : "=f"(r) : "f"(x));
    return r;
}
__device__ __forceinline__ void mma8(float& d0, float& d1, float& d2, float& d3,
                                     unsigned a0, unsigned a1, unsigned a2, unsigned a3,
                                     unsigned b0, unsigned b1) {
    asm("mma.sync.aligned.m16n8k8.row.col.f32.tf32.tf32.f32 "
        "{%0,%1,%2,%3},{%4,%5,%6,%7},{%8,%9},{%0,%1,%2,%3};"
        : "+f"(d0), "+f"(d1), "+f"(d2), "+f"(d3)
        : "r"(a0), "r"(a1), "r"(a2), "r"(a3), "r"(b0), "r"(b1));
}

// -------- inline dtype detect helper --------
__device__ __forceinline__ int detect_is64(const int* __restrict__ ei32,
                                           int t, int* s_flag) {
    int v = ei32[2 * (t & 127) + 1];
    int any = __syncthreads_or(v != 0);
    if (t == 0) *s_flag = !any;
    __syncthreads();
    return *s_flag;
}
__device__ __forceinline__ void decode_edge(const int* __restrict__ ei32,
                                            int is64, int e, int* s, int* d) {
    if (is64) {
        const long long* p = (const long long*)ei32;
        *s = (int)p[e];
        *d = (int)p[EE + e];
    } else {
        *s = ei32[e];
        *d = ei32[EE + e];
    }
}

// ---------------- count degrees (records rank) ----------------
__global__ void count_kernel(const int* __restrict__ ei32) {
    __shared__ int s_is64;
    int t = threadIdx.x;
    int is64 = detect_is64(ei32, t, &s_is64);
    int e = blockIdx.x * 256 + t;
    if (e >= EE) return;
    int s, d;
    decode_edge(ei32, is64, e, &s, &d);
    g_rank[e] = atomicAdd(&g_cnt[d], 1);
}

// ------- warp-autonomous encoder GEMM: x[N,128] @ W[128,64] + b ----------
#define WSE 72    // Ws stride (64-wide +8 pad)
__global__ void __launch_bounds__(128) encoder_kernel(
    const float* __restrict__ x, const float* __restrict__ W,
    const float* __restrict__ b) {
    __shared__ unsigned Ws[128 * WSE];
    __shared__ float    Xs[4][16 * 132];
    __shared__ float    bs[64];
    int tid = threadIdx.x;
    int lane = tid & 31, w = tid >> 5;
    int g = lane >> 2, t = lane & 3;

    for (int i = tid; i < 128 * 64; i += 128)
        Ws[(i >> 6) * WSE + (i & 63)] = f2tf(W[i]);
    if (tid < 64) bs[tid] = b[tid];
    __syncthreads();

    float* Xsw = Xs[w];
    for (int tile = blockIdx.x * 4 + w; tile < NWT; tile += gridDim.x * 4) {
        int r0 = tile * 16;
        __syncwarp();
        const float4* X4 = (const float4*)(x + (size_t)r0 * FIN);
        float4* S4 = (float4*)Xsw;
#pragma unroll
        for (int i = 0; i < 16; i++) {
            int idx = lane + i * 32;
            int r = idx >> 5, c4 = idx & 31;
            float4 v = X4[r * 32 + c4];
            float4 o;
            o.x = __uint_as_float(f2tf(v.x));
            o.y = __uint_as_float(f2tf(v.y));
            o.z = __uint_as_float(f2tf(v.z));
            o.w = __uint_as_float(f2tf(v.w));
            S4[r * 33 + c4] = o;
        }
        __syncwarp();

        float acc[8][4];
#pragma unroll
        for (int i = 0; i < 8; i++) {
            acc[i][0] = 0.f; acc[i][1] = 0.f; acc[i][2] = 0.f; acc[i][3] = 0.f;
        }
#pragma unroll
        for (int ks = 0; ks < 16; ks++) {
            int k0 = ks * 8;
            unsigned a0 = __float_as_uint(Xsw[g * 132 + k0 + t]);
            unsigned a1 = __float_as_uint(Xsw[(g + 8) * 132 + k0 + t]);
            unsigned a2 = __float_as_uint(Xsw[g * 132 + k0 + t + 4]);
            unsigned a3 = __float_as_uint(Xsw[(g + 8) * 132 + k0 + t + 4]);
#pragma unroll
            for (int nt = 0; nt < 8; nt++) {
                unsigned b0 = Ws[(k0 + t) * WSE + nt * 8 + g];
                unsigned b1f = Ws[(k0 + t + 4) * WSE + nt * 8 + g];
                mma8(acc[nt][0], acc[nt][1], acc[nt][2], acc[nt][3],
                     a0, a1, a2, a3, b0, b1f);
            }
        }
#pragma unroll
        for (int nt = 0; nt < 8; nt++) {
            int col = nt * 8 + 2 * t;
            float2 bb = *(float2*)&bs[col];
            *(float2*)&g_xenc[(size_t)(r0 + g) * HH + col] =
                make_float2(acc[nt][0] + bb.x, acc[nt][1] + bb.y);
            *(float2*)&g_xenc[(size_t)(r0 + g + 8) * HH + col] =
                make_float2(acc[nt][2] + bb.x, acc[nt][3] + bb.y);
        }
    }
}

// ---- block exclusive scan helper ----
__device__ __forceinline__ int block_excl_scan_256(int v, int* wsum, int t) {
    int lane = t & 31;
    int w = t >> 5;
    int incl = v;
#pragma unroll
    for (int o = 1; o < 32; o <<= 1) {
        int n = __shfl_up_sync(0xffffffffu, incl, o);
        if (lane >= o) incl += n;
    }
    if (lane == 31) wsum[w] = incl;
    __syncthreads();
    if (t == 0) {
        int run = 0;
#pragma unroll
        for (int i = 0; i < 8; i++) { int c = wsum[i]; wsum[i] = run; run += c; }
        wsum[8] = run;
    }
    __syncthreads();
    return incl - v + wsum[w];
}

// ---- single-pass decoupled-lookback scan: g_cnt -> g_off ----
__global__ void scan_lb_kernel() {
    __shared__ int wsum[9];
    __shared__ int s_excl;
    int b = blockIdx.x, t = threadIdx.x;
    int idx = b * 256 + t;
    int v = (idx < NN) ? g_cnt[idx] : 0;
    int excl = block_excl_scan_256(v, wsum, t);
    int total = wsum[8];

    if (t == 0) {
        unsigned long long st = (b == 0)
            ? ((2ULL << 32) | (unsigned)total)
            : ((1ULL << 32) | (unsigned)total);
        atomicExch((unsigned long long*)&g_state[b], st);
        if (b == 0) s_excl = 0;
    }
    if (b > 0 && t < 32) {
        int lane = t;
        int look = b - 1;
        int run = 0;
        while (true) {
            int ip = look - lane;
            unsigned long long s;
            if (ip >= 0) {
                do { s = g_state[ip]; } while ((s >> 32) == 0);
            } else {
                s = (2ULL << 32);
            }
            int isPref = ((s >> 32) == 2u);
            unsigned mask = __ballot_sync(0xffffffffu, isPref);
            int val = (int)(s & 0xffffffffu);
            if (mask) {
                int p = __ffs(mask) - 1;
                int contrib = (lane <= p) ? val : 0;
#pragma unroll
                for (int o = 16; o; o >>= 1) contrib += __shfl_xor_sync(0xffffffffu, contrib, o);
                run += contrib;
                break;
            } else {
                int contrib = val;
#pragma unroll
                for (int o = 16; o; o >>= 1) contrib += __shfl_xor_sync(0xffffffffu, contrib, o);
                run += contrib;
                look -= 32;
            }
        }
        if (lane == 0) {
            s_excl = run;
            atomicExch((unsigned long long*)&g_state[b],
                       (2ULL << 32) | (unsigned)(run + total));
        }
    }
    __syncthreads();
    int base = s_excl;
    if (idx < NN) g_off[idx] = excl + base;
    if (b == SCAN_NBLK - 1 && t == 0) g_off[NN] = EE;
}

// ------- scatter: 4 edges/thread (MLP-4), no atomics (recorded rank) ------
__global__ void scatter_kernel(const int* __restrict__ ei32) {
    __shared__ int s_is64;
    int t = threadIdx.x;
    int is64 = detect_is64(ei32, t, &s_is64);
    int base = blockIdx.x * 1024 + t;

    int e0 = base, e1 = base + 256, e2 = base + 512, e3 = base + 768;
    int s0, d0, s1, d1, s2, d2, s3, d3;
    bool v0 = e0 < EE, v1 = e1 < EE, v2 = e2 < EE, v3 = e3 < EE;
    if (v0) decode_edge(ei32, is64, e0, &s0, &d0);
    if (v1) decode_edge(ei32, is64, e1, &s1, &d1);
    if (v2) decode_edge(ei32, is64, e2, &s2, &d2);
    if (v3) decode_edge(ei32, is64, e3, &s3, &d3);
    int r0 = v0 ? g_rank[e0] : 0;
    int r1 = v1 ? g_rank[e1] : 0;
    int r2 = v2 ? g_rank[e2] : 0;
    int r3 = v3 ? g_rank[e3] : 0;
    int o0 = v0 ? g_off[d0] : 0;
    int o1 = v1 ? g_off[d1] : 0;
    int o2 = v2 ? g_off[d2] : 0;
    int o3 = v3 ? g_off[d3] : 0;
    if (v0) g_srcSorted[o0 + r0] = s0;
    if (v1) g_srcSorted[o1 + r1] = s1;
    if (v2) g_srcSorted[o2 + r2] = s2;
    if (v3) g_srcSorted[o3 + r3] = s3;
}

// ---------------- softmax aggregation ----------------
__global__ void agg_kernel(int sel, const float* __restrict__ tptr) {
    const float4* __restrict__ xin4 = (const float4*)(sel ? g_x1 : g_xenc);
    int gw = (blockIdx.x * blockDim.x + threadIdx.x) >> 5;
    int lane = threadIdx.x & 31;
    if (gw >= NN) return;
    int half = lane >> 4;
    int li = lane & 15;
    float t2 = (*tptr) * 1.44269504f;
    int e0 = g_off[gw], e1 = g_off[gw + 1];

    float S0 = 0.f, S1 = 0.f, S2 = 0.f, S3 = 0.f;
    float A0 = 0.f, A1 = 0.f, A2 = 0.f, A3 = 0.f;

    int e = e0 + half;
    for (; e + 6 < e1; e += 8) {
        int sA = g_srcSorted[e];
        int sB = g_srcSorted[e + 2];
        int sC = g_srcSorted[e + 4];
        int sD = g_srcSorted[e + 6];
        float4 vA = xin4[sA * 16 + li];
        float4 vB = xin4[sB * 16 + li];
        float4 vC = xin4[sC * 16 + li];
        float4 vD = xin4[sD * 16 + li];
        float r, ex;
        r = fmaxf(vA.x, 0.f); ex = ex2f(r * t2); S0 += ex; A0 += r * ex;
        r = fmaxf(vA.y, 0.f); ex = ex2f(r * t2); S1 += ex; A1 += r * ex;
        r = fmaxf(vA.z, 0.f); ex = ex2f(r * t2); S2 += ex; A2 += r * ex;
        r = fmaxf(vA.w, 0.f); ex = ex2f(r * t2); S3 += ex; A3 += r * ex;
        r = fmaxf(vB.x, 0.f); ex = ex2f(r * t2); S0 += ex; A0 += r * ex;
        r = fmaxf(vB.y, 0.f); ex = ex2f(r * t2); S1 += ex; A1 += r * ex;
        r = fmaxf(vB.z, 0.f); ex = ex2f(r * t2); S2 += ex; A2 += r * ex;
        r = fmaxf(vB.w, 0.f); ex = ex2f(r * t2); S3 += ex; A3 += r * ex;
        r = fmaxf(vC.x, 0.f); ex = ex2f(r * t2); S0 += ex; A0 += r * ex;
        r = fmaxf(vC.y, 0.f); ex = ex2f(r * t2); S1 += ex; A1 += r * ex;
        r = fmaxf(vC.z, 0.f); ex = ex2f(r * t2); S2 += ex; A2 += r * ex;
        r = fmaxf(vC.w, 0.f); ex = ex2f(r * t2); S3 += ex; A3 += r * ex;
        r = fmaxf(vD.x, 0.f); ex = ex2f(r * t2); S0 += ex; A0 += r * ex;
        r = fmaxf(vD.y, 0.f); ex = ex2f(r * t2); S1 += ex; A1 += r * ex;
        r = fmaxf(vD.z, 0.f); ex = ex2f(r * t2); S2 += ex; A2 += r * ex;
        r = fmaxf(vD.w, 0.f); ex = ex2f(r * t2); S3 += ex; A3 += r * ex;
    }
    for (; e + 2 < e1; e += 4) {
        int sA = g_srcSorted[e];
        int sB = g_srcSorted[e + 2];
        float4 vA = xin4[sA * 16 + li];
        float4 vB = xin4[sB * 16 + li];
        float r, ex;
        r = fmaxf(vA.x, 0.f); ex = ex2f(r * t2); S0 += ex; A0 += r * ex;
        r = fmaxf(vA.y, 0.f); ex = ex2f(r * t2); S1 += ex; A1 += r * ex;
        r = fmaxf(vA.z, 0.f); ex = ex2f(r * t2); S2 += ex; A2 += r * ex;
        r = fmaxf(vA.w, 0.f); ex = ex2f(r * t2); S3 += ex; A3 += r * ex;
        r = fmaxf(vB.x, 0.f); ex = ex2f(r * t2); S0 += ex; A0 += r * ex;
        r = fmaxf(vB.y, 0.f); ex = ex2f(r * t2); S1 += ex; A1 += r * ex;
        r = fmaxf(vB.z, 0.f); ex = ex2f(r * t2); S2 += ex; A2 += r * ex;
        r = fmaxf(vB.w, 0.f); ex = ex2f(r * t2); S3 += ex; A3 += r * ex;
    }
    if (e < e1) {
        int sA = g_srcSorted[e];
        float4 vA = xin4[sA * 16 + li];
        float r, ex;
        r = fmaxf(vA.x, 0.f); ex = ex2f(r * t2); S0 += ex; A0 += r * ex;
        r = fmaxf(vA.y, 0.f); ex = ex2f(r * t2); S1 += ex; A1 += r * ex;
        r = fmaxf(vA.z, 0.f); ex = ex2f(r * t2); S2 += ex; A2 += r * ex;
        r = fmaxf(vA.w, 0.f); ex = ex2f(r * t2); S3 += ex; A3 += r * ex;
    }
    S0 += __shfl_xor_sync(0xffffffffu, S0, 16);
    S1 += __shfl_xor_sync(0xffffffffu, S1, 16);
    S2 += __shfl_xor_sync(0xffffffffu, S2, 16);
    S3 += __shfl_xor_sync(0xffffffffu, S3, 16);
    A0 += __shfl_xor_sync(0xffffffffu, A0, 16);
    A1 += __shfl_xor_sync(0xffffffffu, A1, 16);
    A2 += __shfl_xor_sync(0xffffffffu, A2, 16);
    A3 += __shfl_xor_sync(0xffffffffu, A3, 16);

    if (half == 0) {
        float4 self = xin4[gw * 16 + li];
        float4 o;
        o.x = A0 / (S0 + 1e-16f) + MSG_EPS + self.x;
        o.y = A1 / (S1 + 1e-16f) + MSG_EPS + self.y;
        o.z = A2 / (S2 + 1e-16f) + MSG_EPS + self.z;
        o.w = A3 / (S3 + 1e-16f) + MSG_EPS + self.w;
        ((float4*)g_tmp)[gw * 16 + li] = o;
    }
}

// -------- warp-autonomous fused MLP via tf32 mma (PDL-aware) --------
#define W1S 136   // 128-wide +8 pad
#define W2S 72    // 64-wide +8 pad
template <int FINAL>
__global__ void __launch_bounds__(128) mlp_kernel(
    const float* __restrict__ W1, const float* __restrict__ b1,
    const float* __restrict__ g1, const float* __restrict__ be1,
    const float* __restrict__ W2, const float* __restrict__ b2,
    const float* __restrict__ ln1g, const float* __restrict__ ln1b,
    const float* __restrict__ ng, const float* __restrict__ nb,
    const float* __restrict__ lw, const float* __restrict__ lb,
    float* __restrict__ out) {
    __shared__ unsigned W1s[64 * W1S];
    __shared__ unsigned W2s[128 * W2S];
    __shared__ float    Xs[4][16 * 68];
    __shared__ float    b1s[128], g1s[128], be1s[128], b2s[64];
    __shared__ float    l1gs[64], l1bs[64], ngs[128], nbs[128], lws[128];

    int tid = threadIdx.x;
    int lane = tid & 31, w = tid >> 5;
    int g = lane >> 2, t = lane & 3;

    // ---- weight prologue: reads ONLY kernel params (overlaps prior kernel) ----
    for (int i = tid; i < 64 * 128; i += 128)
        W1s[(i >> 7) * W1S + (i & 127)] = f2tf(W1[i]);
    for (int i = tid; i < 128 * 64; i += 128)
        W2s[(i >> 6) * W2S + (i & 63)] = f2tf(W2[i]);
    b1s[tid] = b1[tid]; g1s[tid] = g1[tid]; be1s[tid] = be1[tid];
    if (tid < 64) b2s[tid] = b2[tid];
    if (FINAL) {
        if (tid < 64) { l1gs[tid] = ln1g[tid]; l1bs[tid] = ln1b[tid]; }
        ngs[tid] = ng[tid]; nbs[tid] = nb[tid]; lws[tid] = lw[tid];
    }
    float lbv = FINAL ? lb[0] : 0.f;
    __syncthreads();

#if __CUDA_ARCH__ >= 900
    cudaGridDependencySynchronize();   // wait for producer before touching g_tmp/g_x1
#endif

    float* Xsw = Xs[w];
    int srcA = (lane & ~3) | (t >> 1);
    int srcB = srcA + 2;
    bool odd = (t & 1) != 0;

    for (int tile = blockIdx.x * 4 + w; tile < NWT; tile += gridDim.x * 4) {
        int r0 = tile * 16;

        __syncwarp();
        const float4* X4 = (const float4*)(g_tmp + (size_t)r0 * HH);
        float4* S4 = (float4*)Xsw;
#pragma unroll
        for (int i = 0; i < 8; i++) {
            int idx = lane + i * 32;
            int r = idx >> 4, c4 = idx & 15;
            float4 v = X4[r * 16 + c4];
            float4 o;
            o.x = __uint_as_float(f2tf(v.x));
            o.y = __uint_as_float(f2tf(v.y));
            o.z = __uint_as_float(f2tf(v.z));
            o.w = __uint_as_float(f2tf(v.w));
            S4[r * 17 + c4] = o;
        }
        __syncwarp();

        float acc[16][4];
#pragma unroll
        for (int i = 0; i < 16; i++) {
            acc[i][0] = 0.f; acc[i][1] = 0.f; acc[i][2] = 0.f; acc[i][3] = 0.f;
        }
#pragma unroll
        for (int ks = 0; ks < 8; ks++) {
            int k0 = ks * 8;
            unsigned a0 = __float_as_uint(Xsw[g * 68 + k0 + t]);
            unsigned a1 = __float_as_uint(Xsw[(g + 8) * 68 + k0 + t]);
            unsigned a2 = __float_as_uint(Xsw[g * 68 + k0 + t + 4]);
            unsigned a3 = __float_as_uint(Xsw[(g + 8) * 68 + k0 + t + 4]);
#pragma unroll
            for (int nt = 0; nt < 16; nt++) {
                unsigned b0 = W1s[(k0 + t) * W1S + nt * 8 + g];
                unsigned b1f = W1s[(k0 + t + 4) * W1S + nt * 8 + g];
                mma8(acc[nt][0], acc[nt][1], acc[nt][2], acc[nt][3],
                     a0, a1, a2, a3, b0, b1f);
            }
        }

        float sg = 0.f, qg = 0.f, sh = 0.f, qh = 0.f;
#pragma unroll
        for (int nt = 0; nt < 16; nt++) {
            float2 bb = *(float2*)&b1s[nt * 8 + 2 * t];
            acc[nt][0] += bb.x; acc[nt][1] += bb.y;
            acc[nt][2] += bb.x; acc[nt][3] += bb.y;
            sg += acc[nt][0] + acc[nt][1];
            qg += acc[nt][0] * acc[nt][0] + acc[nt][1] * acc[nt][1];
            sh += acc[nt][2] + acc[nt][3];
            qh += acc[nt][2] * acc[nt][2] + acc[nt][3] * acc[nt][3];
        }
        sg += __shfl_xor_sync(~0u, sg, 1); sg += __shfl_xor_sync(~0u, sg, 2);
        qg += __shfl_xor_sync(~0u, qg, 1); qg += __shfl_xor_sync(~0u, qg, 2);
        sh += __shfl_xor_sync(~0u, sh, 1); sh += __shfl_xor_sync(~0u, sh, 2);
        qh += __shfl_xor_sync(~0u, qh, 1); qh += __shfl_xor_sync(~0u, qh, 2);
        float mug = sg * (1.f / HX), muh = sh * (1.f / HX);
        float rg = rsqrtf(qg * (1.f / HX) - mug * mug + 1e-5f);
        float rh = rsqrtf(qh * (1.f / HX) - muh * muh + 1e-5f);
#pragma unroll
        for (int nt = 0; nt < 16; nt++) {
            float2 gg = *(float2*)&g1s[nt * 8 + 2 * t];
            float2 be = *(float2*)&be1s[nt * 8 + 2 * t];
            acc[nt][0] = __uint_as_float(f2tf(fmaxf((acc[nt][0] - mug) * rg * gg.x + be.x, 0.f)));
            acc[nt][1] = __uint_as_float(f2tf(fmaxf((acc[nt][1] - mug) * rg * gg.y + be.y, 0.f)));
            acc[nt][2] = __uint_as_float(f2tf(fmaxf((acc[nt][2] - muh) * rh * gg.x + be.x, 0.f)));
            acc[nt][3] = __uint_as_float(f2tf(fmaxf((acc[nt][3] - muh) * rh * gg.y + be.y, 0.f)));
        }

        float acc2[8][4];
#pragma unroll
        for (int i = 0; i < 8; i++) {
            acc2[i][0] = 0.f; acc2[i][1] = 0.f; acc2[i][2] = 0.f; acc2[i][3] = 0.f;
        }
#pragma unroll
        for (int ks = 0; ks < 16; ks++) {
            int k0 = ks * 8;
            float x0 = __shfl_sync(~0u, acc[ks][0], srcA);
            float x1v = __shfl_sync(~0u, acc[ks][1], srcA);
            float y0 = __shfl_sync(~0u, acc[ks][0], srcB);
            float y1 = __shfl_sync(~0u, acc[ks][1], srcB);
            float z0 = __shfl_sync(~0u, acc[ks][2], srcA);
            float z1 = __shfl_sync(~0u, acc[ks][3], srcA);
            float u0 = __shfl_sync(~0u, acc[ks][2], srcB);
            float u1 = __shfl_sync(~0u, acc[ks][3], srcB);
            unsigned a0 = __float_as_uint(odd ? x1v : x0);
            unsigned a1 = __float_as_uint(odd ? z1 : z0);
            unsigned a2 = __float_as_uint(odd ? y1 : y0);
            unsigned a3 = __float_as_uint(odd ? u1 : u0);
#pragma unroll
            for (int nt = 0; nt < 8; nt++) {
                unsigned b0 = W2s[(k0 + t) * W2S + nt * 8 + g];
                unsigned b1f = W2s[(k0 + t + 4) * W2S + nt * 8 + g];
                mma8(acc2[nt][0], acc2[nt][1], acc2[nt][2], acc2[nt][3],
                     a0, a1, a2, a3, b0, b1f);
            }
        }

        if (!FINAL) {
#pragma unroll
            for (int nt = 0; nt < 8; nt++) {
                float2 bb = *(float2*)&b2s[nt * 8 + 2 * t];
                int col = nt * 8 + 2 * t;
                *(float2*)&g_x1[(size_t)(r0 + g) * HH + col] =
                    make_float2(acc2[nt][0] + bb.x, acc2[nt][1] + bb.y);
                *(float2*)&g_x1[(size_t)(r0 + g + 8) * HH + col] =
                    make_float2(acc2[nt][2] + bb.x, acc2[nt][3] + bb.y);
            }
        } else {
            float hsg = 0.f, hqg = 0.f, hsh = 0.f, hqh = 0.f;
#pragma unroll
            for (int nt = 0; nt < 8; nt++) {
                float2 bb = *(float2*)&b2s[nt * 8 + 2 * t];
                acc2[nt][0] += bb.x; acc2[nt][1] += bb.y;
                acc2[nt][2] += bb.x; acc2[nt][3] += bb.y;
                hsg += acc2[nt][0] + acc2[nt][1];
                hqg += acc2[nt][0] * acc2[nt][0] + acc2[nt][1] * acc2[nt][1];
                hsh += acc2[nt][2] + acc2[nt][3];
                hqh += acc2[nt][2] * acc2[nt][2] + acc2[nt][3] * acc2[nt][3];
            }
            hsg += __shfl_xor_sync(~0u, hsg, 1); hsg += __shfl_xor_sync(~0u, hsg, 2);
            hqg += __shfl_xor_sync(~0u, hqg, 1); hqg += __shfl_xor_sync(~0u, hqg, 2);
            hsh += __shfl_xor_sync(~0u, hsh, 1); hsh += __shfl_xor_sync(~0u, hsh, 2);
            hqh += __shfl_xor_sync(~0u, hqh, 1); hqh += __shfl_xor_sync(~0u, hqh, 2);
            float mu1g = hsg * (1.f / 64.f), mu1h = hsh * (1.f / 64.f);
            float r1g = rsqrtf(hqg * (1.f / 64.f) - mu1g * mu1g + 1e-5f);
            float r1h = rsqrtf(hqh * (1.f / 64.f) - mu1h * mu1h + 1e-5f);

            float hng[8][2], hnh[8][2];
            float2 xg[8], xh[8];
            float s2g = 0.f, q2g = 0.f, s2h = 0.f, q2h = 0.f;
#pragma unroll
            for (int nt = 0; nt < 8; nt++) {
                int col = nt * 8 + 2 * t;
                float2 lg = *(float2*)&l1gs[col];
                float2 lbb = *(float2*)&l1bs[col];
                hng[nt][0] = fmaxf((acc2[nt][0] - mu1g) * r1g * lg.x + lbb.x, 0.f);
                hng[nt][1] = fmaxf((acc2[nt][1] - mu1g) * r1g * lg.y + lbb.y, 0.f);
                hnh[nt][0] = fmaxf((acc2[nt][2] - mu1h) * r1h * lg.x + lbb.x, 0.f);
                hnh[nt][1] = fmaxf((acc2[nt][3] - mu1h) * r1h * lg.y + lbb.y, 0.f);
                xg[nt] = *(const float2*)&g_x1[(size_t)(r0 + g) * HH + col];
                xh[nt] = *(const float2*)&g_x1[(size_t)(r0 + g + 8) * HH + col];
                s2g += xg[nt].x + xg[nt].y + hng[nt][0] + hng[nt][1];
                q2g += xg[nt].x * xg[nt].x + xg[nt].y * xg[nt].y
                     + hng[nt][0] * hng[nt][0] + hng[nt][1] * hng[nt][1];
                s2h += xh[nt].x + xh[nt].y + hnh[nt][0] + hnh[nt][1];
                q2h += xh[nt].x * xh[nt].x + xh[nt].y * xh[nt].y
                     + hnh[nt][0] * hnh[nt][0] + hnh[nt][1] * hnh[nt][1];
            }
            s2g += __shfl_xor_sync(~0u, s2g, 1); s2g += __shfl_xor_sync(~0u, s2g, 2);
            q2g += __shfl_xor_sync(~0u, q2g, 1); q2g += __shfl_xor_sync(~0u, q2g, 2);
            s2h += __shfl_xor_sync(~0u, s2h, 1); s2h += __shfl_xor_sync(~0u, s2h, 2);
            q2h += __shfl_xor_sync(~0u, q2h, 1); q2h += __shfl_xor_sync(~0u, q2h, 2);
            float mu2g = s2g * (1.f / 128.f), mu2h = s2h * (1.f / 128.f);
            float r2g = rsqrtf(q2g * (1.f / 128.f) - mu2g * mu2g + 1e-5f);
            float r2h = rsqrtf(q2h * (1.f / 128.f) - mu2h * mu2h + 1e-5f);

            float dg = 0.f, dh = 0.f;
#pragma unroll
            for (int nt = 0; nt < 8; nt++) {
                int col = nt * 8 + 2 * t;
                float2 ngx = *(float2*)&ngs[col];
                float2 nbx = *(float2*)&nbs[col];
                float2 ngh2 = *(float2*)&ngs[64 + col];
                float2 nbh2 = *(float2*)&nbs[64 + col];
                float2 lwx = *(float2*)&lws[col];
                float2 lwh2 = *(float2*)&lws[64 + col];
                dg += fmaxf((xg[nt].x - mu2g) * r2g * ngx.x + nbx.x, 0.f) * lwx.x
                    + fmaxf((xg[nt].y - mu2g) * r2g * ngx.y + nbx.y, 0.f) * lwx.y
                    + fmaxf((hng[nt][0] - mu2g) * r2g * ngh2.x + nbh2.x, 0.f) * lwh2.x
                    + fmaxf((hng[nt][1] - mu2g) * r2g * ngh2.y + nbh2.y, 0.f) * lwh2.y;
                dh += fmaxf((xh[nt].x - mu2h) * r2h * ngx.x + nbx.x, 0.f) * lwx.x
                    + fmaxf((xh[nt].y - mu2h) * r2h * ngx.y + nbx.y, 0.f) * lwx.y
                    + fmaxf((hnh[nt][0] - mu2h) * r2h * ngh2.x + nbh2.x, 0.f) * lwh2.x
                    + fmaxf((hnh[nt][1] - mu2h) * r2h * ngh2.y + nbh2.y, 0.f) * lwh2.y;
            }
            dg += __shfl_xor_sync(~0u, dg, 1); dg += __shfl_xor_sync(~0u, dg, 2);
            dh += __shfl_xor_sync(~0u, dh, 1); dh += __shfl_xor_sync(~0u, dh, 2);
            if (t == 0) {
                out[r0 + g] = dg + lbv;
                out[r0 + g + 8] = dh + lbv;
            }
        }
    }

    if (FINAL) {
        for (int i = blockIdx.x * blockDim.x + tid; i < NN; i += gridDim.x * blockDim.x)
            g_cnt[i] = 0;
        int i = blockIdx.x * blockDim.x + tid;
        if (i < SCAN_NBLK) *((unsigned long long*)&g_state[i]) = 0ULL;
    }
}

// ---------------- launch ----------------
extern "C" void kernel_launch(void* const* d_in, const int* in_sizes, int n_in,
                              void* d_out, int out_size) {
    const float* x    = (const float*)d_in[0];
    const void*  ei   = d_in[1];
    const float* encW = (const float*)d_in[2];
    const float* encB = (const float*)d_in[3];
    const float* t    = (const float*)d_in[4];
    const float* W1   = (const float*)d_in[5];
    const float* b1   = (const float*)d_in[6];
    const float* g1   = (const float*)d_in[7];
    const float* be1  = (const float*)d_in[8];
    const float* W2   = (const float*)d_in[9];
    const float* b2   = (const float*)d_in[10];
    const float* ln1g = (const float*)d_in[11];
    const float* ln1b = (const float*)d_in[12];
    const float* ng   = (const float*)d_in[13];
    const float* nb   = (const float*)d_in[14];
    const float* lw   = (const float*)d_in[15];
    const float* lb   = (const float*)d_in[16];
    float* out = (float*)d_out;

    const int AGG_BLOCKS = (NN * 32 + 255) / 256;

    cudaStream_t sB;
    cudaEvent_t evF, evJ;
    cudaStreamCreateWithFlags(&sB, cudaStreamNonBlocking);
    cudaEventCreateWithFlags(&evF, cudaEventDisableTiming);
    cudaEventCreateWithFlags(&evJ, cudaEventDisableTiming);

    // fork: encoder runs on sB, concurrent with the CSR chain
    cudaEventRecord(evF, 0);
    cudaStreamWaitEvent(sB, evF, 0);
    encoder_kernel<<<296, 128, 0, sB>>>(x, encW, encB);
    cudaEventRecord(evJ, sB);

    count_kernel<<<CNT_BLOCKS, 256>>>((const int*)ei);
    scan_lb_kernel<<<SCAN_NBLK, 256>>>();
    scatter_kernel<<<SCAT_BLOCKS, 256>>>((const int*)ei);

    // join: agg1 needs both scatter (stream 0) and encoder (sB)
    cudaStreamWaitEvent(0, evJ, 0);
    agg_kernel<<<AGG_BLOCKS, 256>>>(0, t);

    // mlp launches use PDL: weight prologue overlaps the preceding agg's tail
    cudaLaunchConfig_t cfg = {};
    cfg.gridDim = dim3(296, 1, 1);
    cfg.blockDim = dim3(128, 1, 1);
    cudaLaunchAttribute pdlAttr[1];
    pdlAttr[0].id = cudaLaunchAttributeProgrammaticStreamSerialization;
    pdlAttr[0].val.programmaticStreamSerializationAllowed = 1;
    cfg.attrs = pdlAttr;
    cfg.numAttrs = 1;
    cfg.stream = 0;

    cudaLaunchKernelEx(&cfg, mlp_kernel<0>, W1, b1, g1, be1, W2, b2,
                       ln1g, ln1b, ng, nb, lw, lb, out);
    agg_kernel<<<AGG_BLOCKS, 256>>>(1, t);
    cudaLaunchKernelEx(&cfg, mlp_kernel<1>, W1, b1, g1, be1, W2, b2,
                       ln1g, ln1b, ng, nb, lw, lb, out);
}

// round 16
// speedup vs baseline: 1.0436x; 1.0429x over previous
#include <cuda_runtime.h>

#define NN 50000
#define EE 800000
#define FIN 128
#define HH 64
#define HX 128   // 2H

#define MSG_EPS 1e-7f
#define SCAN_NBLK ((NN + 255) / 256)    // 196
#define EDGE_BLOCKS ((EE + 255) / 256)  // 3125
#define NWT (NN / 16)                   // 3125 warp-tiles (exact)

#if !defined(__CUDA_ARCH__) || __CUDA_ARCH__ >= 900
#define PDL_TRIGGER() cudaTriggerProgrammaticLaunchCompletion()
#define PDL_WAIT()    cudaGridDependencySynchronize()
#else
#define PDL_TRIGGER()
#define PDL_WAIT()
#endif

// ---------------- device scratch (no allocation allowed) ----------------
__device__ int   g_srcSorted[EE];
__device__ int   g_rank[EE];           // edge's arrival rank within its dst
__device__ int   g_cnt[NN];            // 0 at run start (zeroed at run end)
__device__ int   g_off[NN + 1];
__device__ volatile unsigned long long g_state[SCAN_NBLK];  // 0 at run start
__device__ float g_xenc[NN * HH];
__device__ float g_tmp[NN * HH];
__device__ float g_x1[NN * HH];

// ---------------- tf32 mma helpers ----------------
__device__ __forceinline__ unsigned f2tf(float f) {
    unsigned r;
    asm("cvt.rna.tf32.f32 %0, %1;" : "=r"(r) : "f"(f));
    return r;
}
__device__ __forceinline__ float ex2f(float x) {
    float r;
    asm("ex2.approx.ftz.f32 %0, %1;" : "=f"(r) : "f"(x));
    return r;
}
__device__ __forceinline__ void mma8(float& d0, float& d1, float& d2, float& d3,
                                     unsigned a0, unsigned a1, unsigned a2, unsigned a3,
                                     unsigned b0, unsigned b1) {
    asm("mma.sync.aligned.m16n8k8.row.col.f32.tf32.tf32.f32 "
        "{%0,%1,%2,%3},{%4,%5,%6,%7},{%8,%9},{%0,%1,%2,%3};"
        : "+f"(d0), "+f"(d1), "+f"(d2), "+f"(d3)
        : "r"(a0), "r"(a1), "r"(a2), "r"(a3), "r"(b0), "r"(b1));
}

// -------- inline dtype detect helper --------
__device__ __forceinline__ int detect_is64(const int* __restrict__ ei32,
                                           int t, int* s_flag) {
    int v = ei32[2 * (t & 127) + 1];
    int any = __syncthreads_or(v != 0);
    if (t == 0) *s_flag = !any;
    __syncthreads();
    return *s_flag;
}
__device__ __forceinline__ void decode_edge(const int* __restrict__ ei32,
                                            int is64, int e, int* s, int* d) {
    if (is64) {
        const long long* p = (const long long*)ei32;
        *s = (int)p[e];
        *d = (int)p[EE + e];
    } else {
        *s = ei32[e];
        *d = ei32[EE + e];
    }
}

// ---------------- count degrees (records rank) ----------------
__global__ void count_kernel(const int* __restrict__ ei32) {
    __shared__ int s_is64;
    int t = threadIdx.x;
    int is64 = detect_is64(ei32, t, &s_is64);
    int e = blockIdx.x * 256 + t;
    if (e >= EE) return;
    int s, d;
    decode_edge(ei32, is64, e, &s, &d);
    g_rank[e] = atomicAdd(&g_cnt[d], 1);
}

// ------- warp-autonomous encoder GEMM: x[N,128] @ W[128,64] + b ----------
#define WSE 72    // Ws stride (64-wide +8 pad)
__global__ void __launch_bounds__(128) encoder_kernel(
    const float* __restrict__ x, const float* __restrict__ W,
    const float* __restrict__ b) {
    __shared__ unsigned Ws[128 * WSE];
    __shared__ float    Xs[4][16 * 132];
    __shared__ float    bs[64];
    int tid = threadIdx.x;
    int lane = tid & 31, w = tid >> 5;
    int g = lane >> 2, t = lane & 3;

    for (int i = tid; i < 128 * 64; i += 128)
        Ws[(i >> 6) * WSE + (i & 63)] = f2tf(W[i]);
    if (tid < 64) bs[tid] = b[tid];
    __syncthreads();

    float* Xsw = Xs[w];
    for (int tile = blockIdx.x * 4 + w; tile < NWT; tile += gridDim.x * 4) {
        int r0 = tile * 16;
        __syncwarp();
        const float4* X4 = (const float4*)(x + (size_t)r0 * FIN);
        float4* S4 = (float4*)Xsw;
#pragma unroll
        for (int i = 0; i < 16; i++) {
            int idx = lane + i * 32;
            int r = idx >> 5, c4 = idx & 31;
            float4 v = X4[r * 32 + c4];
            float4 o;
            o.x = __uint_as_float(f2tf(v.x));
            o.y = __uint_as_float(f2tf(v.y));
            o.z = __uint_as_float(f2tf(v.z));
            o.w = __uint_as_float(f2tf(v.w));
            S4[r * 33 + c4] = o;
        }
        __syncwarp();

        float acc[8][4];
#pragma unroll
        for (int i = 0; i < 8; i++) {
            acc[i][0] = 0.f; acc[i][1] = 0.f; acc[i][2] = 0.f; acc[i][3] = 0.f;
        }
#pragma unroll
        for (int ks = 0; ks < 16; ks++) {
            int k0 = ks * 8;
            unsigned a0 = __float_as_uint(Xsw[g * 132 + k0 + t]);
            unsigned a1 = __float_as_uint(Xsw[(g + 8) * 132 + k0 + t]);
            unsigned a2 = __float_as_uint(Xsw[g * 132 + k0 + t + 4]);
            unsigned a3 = __float_as_uint(Xsw[(g + 8) * 132 + k0 + t + 4]);
#pragma unroll
            for (int nt = 0; nt < 8; nt++) {
                unsigned b0 = Ws[(k0 + t) * WSE + nt * 8 + g];
                unsigned b1f = Ws[(k0 + t + 4) * WSE + nt * 8 + g];
                mma8(acc[nt][0], acc[nt][1], acc[nt][2], acc[nt][3],
                     a0, a1, a2, a3, b0, b1f);
            }
        }
#pragma unroll
        for (int nt = 0; nt < 8; nt++) {
            int col = nt * 8 + 2 * t;
            float2 bb = *(float2*)&bs[col];
            *(float2*)&g_xenc[(size_t)(r0 + g) * HH + col] =
                make_float2(acc[nt][0] + bb.x, acc[nt][1] + bb.y);
            *(float2*)&g_xenc[(size_t)(r0 + g + 8) * HH + col] =
                make_float2(acc[nt][2] + bb.x, acc[nt][3] + bb.y);
        }
    }
}

// ---- block exclusive scan helper ----
__device__ __forceinline__ int block_excl_scan_256(int v, int* wsum, int t) {
    int lane = t & 31;
    int w = t >> 5;
    int incl = v;
#pragma unroll
    for (int o = 1; o < 32; o <<= 1) {
        int n = __shfl_up_sync(0xffffffffu, incl, o);
        if (lane >= o) incl += n;
    }
    if (lane == 31) wsum[w] = incl;
    __syncthreads();
    if (t == 0) {
        int run = 0;
#pragma unroll
        for (int i = 0; i < 8; i++) { int c = wsum[i]; wsum[i] = run; run += c; }
        wsum[8] = run;
    }
    __syncthreads();
    return incl - v + wsum[w];
}

// ---- single-pass decoupled-lookback scan: g_cnt -> g_off ----
__global__ void scan_lb_kernel() {
    __shared__ int wsum[9];
    __shared__ int s_excl;
    int b = blockIdx.x, t = threadIdx.x;
    int idx = b * 256 + t;
    int v = (idx < NN) ? g_cnt[idx] : 0;
    int excl = block_excl_scan_256(v, wsum, t);
    int total = wsum[8];

    if (t == 0) {
        unsigned long long st = (b == 0)
            ? ((2ULL << 32) | (unsigned)total)
            : ((1ULL << 32) | (unsigned)total);
        atomicExch((unsigned long long*)&g_state[b], st);
        if (b == 0) s_excl = 0;
    }
    if (b > 0 && t < 32) {
        int lane = t;
        int look = b - 1;
        int run = 0;
        while (true) {
            int ip = look - lane;
            unsigned long long s;
            if (ip >= 0) {
                do { s = g_state[ip]; } while ((s >> 32) == 0);
            } else {
                s = (2ULL << 32);
            }
            int isPref = ((s >> 32) == 2u);
            unsigned mask = __ballot_sync(0xffffffffu, isPref);
            int val = (int)(s & 0xffffffffu);
            if (mask) {
                int p = __ffs(mask) - 1;
                int contrib = (lane <= p) ? val : 0;
#pragma unroll
                for (int o = 16; o; o >>= 1) contrib += __shfl_xor_sync(0xffffffffu, contrib, o);
                run += contrib;
                break;
            } else {
                int contrib = val;
#pragma unroll
                for (int o = 16; o; o >>= 1) contrib += __shfl_xor_sync(0xffffffffu, contrib, o);
                run += contrib;
                look -= 32;
            }
        }
        if (lane == 0) {
            s_excl = run;
            atomicExch((unsigned long long*)&g_state[b],
                       (2ULL << 32) | (unsigned)(run + total));
        }
    }
    __syncthreads();
    int base = s_excl;
    if (idx < NN) g_off[idx] = excl + base;
    if (b == SCAN_NBLK - 1 && t == 0) g_off[NN] = EE;
}

// ------- scatter: no atomics (recorded rank); triggers PDL release --------
__global__ void scatter_kernel(const int* __restrict__ ei32) {
    __shared__ int s_is64;
    int t = threadIdx.x;
    int is64 = detect_is64(ei32, t, &s_is64);
    int e = blockIdx.x * blockDim.x + t;
    if (e < EE) {
        int s, d;
        decode_edge(ei32, is64, e, &s, &d);
        g_srcSorted[g_off[d] + g_rank[e]] = s;
    }
    PDL_TRIGGER();
}

// ---------------- softmax aggregation (PDL producer + consumer) ----------
__global__ void agg_kernel(int sel, const float* __restrict__ tptr) {
    const float4* __restrict__ xin4 = (const float4*)(sel ? g_x1 : g_xenc);
    int gw = (blockIdx.x * blockDim.x + threadIdx.x) >> 5;
    int lane = threadIdx.x & 31;
    int half = lane >> 4;
    int li = lane & 15;
    float t2 = (*tptr) * 1.44269504f;
    // g_off/g_srcSorted were written 2+ kernels upstream of the immediate
    // producer (mlp1 or scatter tail) except: sel==0 producer is scatter,
    // which writes g_srcSorted. So only pre-read g_off here.
    int e0 = g_off[gw], e1 = g_off[gw + 1];

    PDL_WAIT();   // producer (scatter / mlp1) writes now visible

    float S0 = 0.f, S1 = 0.f, S2 = 0.f, S3 = 0.f;
    float A0 = 0.f, A1 = 0.f, A2 = 0.f, A3 = 0.f;

    int e = e0 + half;
    for (; e + 6 < e1; e += 8) {
        int sA = g_srcSorted[e];
        int sB = g_srcSorted[e + 2];
        int sC = g_srcSorted[e + 4];
        int sD = g_srcSorted[e + 6];
        float4 vA = xin4[sA * 16 + li];
        float4 vB = xin4[sB * 16 + li];
        float4 vC = xin4[sC * 16 + li];
        float4 vD = xin4[sD * 16 + li];
        float r, ex;
        r = fmaxf(vA.x, 0.f); ex = ex2f(r * t2); S0 += ex; A0 += r * ex;
        r = fmaxf(vA.y, 0.f); ex = ex2f(r * t2); S1 += ex; A1 += r * ex;
        r = fmaxf(vA.z, 0.f); ex = ex2f(r * t2); S2 += ex; A2 += r * ex;
        r = fmaxf(vA.w, 0.f); ex = ex2f(r * t2); S3 += ex; A3 += r * ex;
        r = fmaxf(vB.x, 0.f); ex = ex2f(r * t2); S0 += ex; A0 += r * ex;
        r = fmaxf(vB.y, 0.f); ex = ex2f(r * t2); S1 += ex; A1 += r * ex;
        r = fmaxf(vB.z, 0.f); ex = ex2f(r * t2); S2 += ex; A2 += r * ex;
        r = fmaxf(vB.w, 0.f); ex = ex2f(r * t2); S3 += ex; A3 += r * ex;
        r = fmaxf(vC.x, 0.f); ex = ex2f(r * t2); S0 += ex; A0 += r * ex;
        r = fmaxf(vC.y, 0.f); ex = ex2f(r * t2); S1 += ex; A1 += r * ex;
        r = fmaxf(vC.z, 0.f); ex = ex2f(r * t2); S2 += ex; A2 += r * ex;
        r = fmaxf(vC.w, 0.f); ex = ex2f(r * t2); S3 += ex; A3 += r * ex;
        r = fmaxf(vD.x, 0.f); ex = ex2f(r * t2); S0 += ex; A0 += r * ex;
        r = fmaxf(vD.y, 0.f); ex = ex2f(r * t2); S1 += ex; A1 += r * ex;
        r = fmaxf(vD.z, 0.f); ex = ex2f(r * t2); S2 += ex; A2 += r * ex;
        r = fmaxf(vD.w, 0.f); ex = ex2f(r * t2); S3 += ex; A3 += r * ex;
    }
    for (; e + 2 < e1; e += 4) {
        int sA = g_srcSorted[e];
        int sB = g_srcSorted[e + 2];
        float4 vA = xin4[sA * 16 + li];
        float4 vB = xin4[sB * 16 + li];
        float r, ex;
        r = fmaxf(vA.x, 0.f); ex = ex2f(r * t2); S0 += ex; A0 += r * ex;
        r = fmaxf(vA.y, 0.f); ex = ex2f(r * t2); S1 += ex; A1 += r * ex;
        r = fmaxf(vA.z, 0.f); ex = ex2f(r * t2); S2 += ex; A2 += r * ex;
        r = fmaxf(vA.w, 0.f); ex = ex2f(r * t2); S3 += ex; A3 += r * ex;
        r = fmaxf(vB.x, 0.f); ex = ex2f(r * t2); S0 += ex; A0 += r * ex;
        r = fmaxf(vB.y, 0.f); ex = ex2f(r * t2); S1 += ex; A1 += r * ex;
        r = fmaxf(vB.z, 0.f); ex = ex2f(r * t2); S2 += ex; A2 += r * ex;
        r = fmaxf(vB.w, 0.f); ex = ex2f(r * t2); S3 += ex; A3 += r * ex;
    }
    if (e < e1) {
        int sA = g_srcSorted[e];
        float4 vA = xin4[sA * 16 + li];
        float r, ex;
        r = fmaxf(vA.x, 0.f); ex = ex2f(r * t2); S0 += ex; A0 += r * ex;
        r = fmaxf(vA.y, 0.f); ex = ex2f(r * t2); S1 += ex; A1 += r * ex;
        r = fmaxf(vA.z, 0.f); ex = ex2f(r * t2); S2 += ex; A2 += r * ex;
        r = fmaxf(vA.w, 0.f); ex = ex2f(r * t2); S3 += ex; A3 += r * ex;
    }
    S0 += __shfl_xor_sync(0xffffffffu, S0, 16);
    S1 += __shfl_xor_sync(0xffffffffu, S1, 16);
    S2 += __shfl_xor_sync(0xffffffffu, S2, 16);
    S3 += __shfl_xor_sync(0xffffffffu, S3, 16);
    A0 += __shfl_xor_sync(0xffffffffu, A0, 16);
    A1 += __shfl_xor_sync(0xffffffffu, A1, 16);
    A2 += __shfl_xor_sync(0xffffffffu, A2, 16);
    A3 += __shfl_xor_sync(0xffffffffu, A3, 16);

    if (half == 0) {
        float4 self = xin4[gw * 16 + li];
        float4 o;
        o.x = A0 / (S0 + 1e-16f) + MSG_EPS + self.x;
        o.y = A1 / (S1 + 1e-16f) + MSG_EPS + self.y;
        o.z = A2 / (S2 + 1e-16f) + MSG_EPS + self.z;
        o.w = A3 / (S3 + 1e-16f) + MSG_EPS + self.w;
        ((float4*)g_tmp)[gw * 16 + li] = o;
    }
    PDL_TRIGGER();   // release the dependent mlp's main phase
}

// -------- warp-autonomous fused MLP via tf32 mma (PDL both ways) --------
#define W1S 136   // 128-wide +8 pad
#define W2S 72    // 64-wide +8 pad
template <int FINAL>
__global__ void __launch_bounds__(128) mlp_kernel(
    const float* __restrict__ W1, const float* __restrict__ b1,
    const float* __restrict__ g1, const float* __restrict__ be1,
    const float* __restrict__ W2, const float* __restrict__ b2,
    const float* __restrict__ ln1g, const float* __restrict__ ln1b,
    const float* __restrict__ ng, const float* __restrict__ nb,
    const float* __restrict__ lw, const float* __restrict__ lb,
    float* __restrict__ out) {
    __shared__ unsigned W1s[64 * W1S];
    __shared__ unsigned W2s[128 * W2S];
    __shared__ float    Xs[4][16 * 68];
    __shared__ float    b1s[128], g1s[128], be1s[128], b2s[64];
    __shared__ float    l1gs[64], l1bs[64], ngs[128], nbs[128], lws[128];

    int tid = threadIdx.x;
    int lane = tid & 31, w = tid >> 5;
    int g = lane >> 2, t = lane & 3;

    // weight prologue: reads only input buffers (overlaps producer tail)
    for (int i = tid; i < 64 * 128; i += 128)
        W1s[(i >> 7) * W1S + (i & 127)] = f2tf(W1[i]);
    for (int i = tid; i < 128 * 64; i += 128)
        W2s[(i >> 6) * W2S + (i & 63)] = f2tf(W2[i]);
    b1s[tid] = b1[tid]; g1s[tid] = g1[tid]; be1s[tid] = be1[tid];
    if (tid < 64) b2s[tid] = b2[tid];
    if (FINAL) {
        if (tid < 64) { l1gs[tid] = ln1g[tid]; l1bs[tid] = ln1b[tid]; }
        ngs[tid] = ng[tid]; nbs[tid] = nb[tid]; lws[tid] = lw[tid];
    }
    float lbv = FINAL ? lb[0] : 0.f;
    __syncthreads();

    PDL_WAIT();   // producer agg's g_tmp (and mlp1's g_x1 for FINAL) visible

    float* Xsw = Xs[w];
    int srcA = (lane & ~3) | (t >> 1);
    int srcB = srcA + 2;
    bool odd = (t & 1) != 0;

    for (int tile = blockIdx.x * 4 + w; tile < NWT; tile += gridDim.x * 4) {
        int r0 = tile * 16;

        __syncwarp();
        const float4* X4 = (const float4*)(g_tmp + (size_t)r0 * HH);
        float4* S4 = (float4*)Xsw;
#pragma unroll
        for (int i = 0; i < 8; i++) {
            int idx = lane + i * 32;
            int r = idx >> 4, c4 = idx & 15;
            float4 v = X4[r * 16 + c4];
            float4 o;
            o.x = __uint_as_float(f2tf(v.x));
            o.y = __uint_as_float(f2tf(v.y));
            o.z = __uint_as_float(f2tf(v.z));
            o.w = __uint_as_float(f2tf(v.w));
            S4[r * 17 + c4] = o;
        }
        __syncwarp();

        float acc[16][4];
#pragma unroll
        for (int i = 0; i < 16; i++) {
            acc[i][0] = 0.f; acc[i][1] = 0.f; acc[i][2] = 0.f; acc[i][3] = 0.f;
        }
#pragma unroll
        for (int ks = 0; ks < 8; ks++) {
            int k0 = ks * 8;
            unsigned a0 = __float_as_uint(Xsw[g * 68 + k0 + t]);
            unsigned a1 = __float_as_uint(Xsw[(g + 8) * 68 + k0 + t]);
            unsigned a2 = __float_as_uint(Xsw[g * 68 + k0 + t + 4]);
            unsigned a3 = __float_as_uint(Xsw[(g + 8) * 68 + k0 + t + 4]);
#pragma unroll
            for (int nt = 0; nt < 16; nt++) {
                unsigned b0 = W1s[(k0 + t) * W1S + nt * 8 + g];
                unsigned b1f = W1s[(k0 + t + 4) * W1S + nt * 8 + g];
                mma8(acc[nt][0], acc[nt][1], acc[nt][2], acc[nt][3],
                     a0, a1, a2, a3, b0, b1f);
            }
        }

        float sg = 0.f, qg = 0.f, sh = 0.f, qh = 0.f;
#pragma unroll
        for (int nt = 0; nt < 16; nt++) {
            float2 bb = *(float2*)&b1s[nt * 8 + 2 * t];
            acc[nt][0] += bb.x; acc[nt][1] += bb.y;
            acc[nt][2] += bb.x; acc[nt][3] += bb.y;
            sg += acc[nt][0] + acc[nt][1];
            qg += acc[nt][0] * acc[nt][0] + acc[nt][1] * acc[nt][1];
            sh += acc[nt][2] + acc[nt][3];
            qh += acc[nt][2] * acc[nt][2] + acc[nt][3] * acc[nt][3];
        }
        sg += __shfl_xor_sync(~0u, sg, 1); sg += __shfl_xor_sync(~0u, sg, 2);
        qg += __shfl_xor_sync(~0u, qg, 1); qg += __shfl_xor_sync(~0u, qg, 2);
        sh += __shfl_xor_sync(~0u, sh, 1); sh += __shfl_xor_sync(~0u, sh, 2);
        qh += __shfl_xor_sync(~0u, qh, 1); qh += __shfl_xor_sync(~0u, qh, 2);
        float mug = sg * (1.f / HX), muh = sh * (1.f / HX);
        float rg = rsqrtf(qg * (1.f / HX) - mug * mug + 1e-5f);
        float rh = rsqrtf(qh * (1.f / HX) - muh * muh + 1e-5f);
#pragma unroll
        for (int nt = 0; nt < 16; nt++) {
            float2 gg = *(float2*)&g1s[nt * 8 + 2 * t];
            float2 be = *(float2*)&be1s[nt * 8 + 2 * t];
            acc[nt][0] = __uint_as_float(f2tf(fmaxf((acc[nt][0] - mug) * rg * gg.x + be.x, 0.f)));
            acc[nt][1] = __uint_as_float(f2tf(fmaxf((acc[nt][1] - mug) * rg * gg.y + be.y, 0.f)));
            acc[nt][2] = __uint_as_float(f2tf(fmaxf((acc[nt][2] - muh) * rh * gg.x + be.x, 0.f)));
            acc[nt][3] = __uint_as_float(f2tf(fmaxf((acc[nt][3] - muh) * rh * gg.y + be.y, 0.f)));
        }

        float acc2[8][4];
#pragma unroll
        for (int i = 0; i < 8; i++) {
            acc2[i][0] = 0.f; acc2[i][1] = 0.f; acc2[i][2] = 0.f; acc2[i][3] = 0.f;
        }
#pragma unroll
        for (int ks = 0; ks < 16; ks++) {
            int k0 = ks * 8;
            float x0 = __shfl_sync(~0u, acc[ks][0], srcA);
            float x1v = __shfl_sync(~0u, acc[ks][1], srcA);
            float y0 = __shfl_sync(~0u, acc[ks][0], srcB);
            float y1 = __shfl_sync(~0u, acc[ks][1], srcB);
            float z0 = __shfl_sync(~0u, acc[ks][2], srcA);
            float z1 = __shfl_sync(~0u, acc[ks][3], srcA);
            float u0 = __shfl_sync(~0u, acc[ks][2], srcB);
            float u1 = __shfl_sync(~0u, acc[ks][3], srcB);
            unsigned a0 = __float_as_uint(odd ? x1v : x0);
            unsigned a1 = __float_as_uint(odd ? z1 : z0);
            unsigned a2 = __float_as_uint(odd ? y1 : y0);
            unsigned a3 = __float_as_uint(odd ? u1 : u0);
#pragma unroll
            for (int nt = 0; nt < 8; nt++) {
                unsigned b0 = W2s[(k0 + t) * W2S + nt * 8 + g];
                unsigned b1f = W2s[(k0 + t + 4) * W2S + nt * 8 + g];
                mma8(acc2[nt][0], acc2[nt][1], acc2[nt][2], acc2[nt][3],
                     a0, a1, a2, a3, b0, b1f);
            }
        }

        if (!FINAL) {
#pragma unroll
            for (int nt = 0; nt < 8; nt++) {
                float2 bb = *(float2*)&b2s[nt * 8 + 2 * t];
                int col = nt * 8 + 2 * t;
                *(float2*)&g_x1[(size_t)(r0 + g) * HH + col] =
                    make_float2(acc2[nt][0] + bb.x, acc2[nt][1] + bb.y);
                *(float2*)&g_x1[(size_t)(r0 + g + 8) * HH + col] =
                    make_float2(acc2[nt][2] + bb.x, acc2[nt][3] + bb.y);
            }
        } else {
            float hsg = 0.f, hqg = 0.f, hsh = 0.f, hqh = 0.f;
#pragma unroll
            for (int nt = 0; nt < 8; nt++) {
                float2 bb = *(float2*)&b2s[nt * 8 + 2 * t];
                acc2[nt][0] += bb.x; acc2[nt][1] += bb.y;
                acc2[nt][2] += bb.x; acc2[nt][3] += bb.y;
                hsg += acc2[nt][0] + acc2[nt][1];
                hqg += acc2[nt][0] * acc2[nt][0] + acc2[nt][1] * acc2[nt][1];
                hsh += acc2[nt][2] + acc2[nt][3];
                hqh += acc2[nt][2] * acc2[nt][2] + acc2[nt][3] * acc2[nt][3];
            }
            hsg += __shfl_xor_sync(~0u, hsg, 1); hsg += __shfl_xor_sync(~0u, hsg, 2);
            hqg += __shfl_xor_sync(~0u, hqg, 1); hqg += __shfl_xor_sync(~0u, hqg, 2);
            hsh += __shfl_xor_sync(~0u, hsh, 1); hsh += __shfl_xor_sync(~0u, hsh, 2);
            hqh += __shfl_xor_sync(~0u, hqh, 1); hqh += __shfl_xor_sync(~0u, hqh, 2);
            float mu1g = hsg * (1.f / 64.f), mu1h = hsh * (1.f / 64.f);
            float r1g = rsqrtf(hqg * (1.f / 64.f) - mu1g * mu1g + 1e-5f);
            float r1h = rsqrtf(hqh * (1.f / 64.f) - mu1h * mu1h + 1e-5f);

            float hng[8][2], hnh[8][2];
            float2 xg[8], xh[8];
            float s2g = 0.f, q2g = 0.f, s2h = 0.f, q2h = 0.f;
#pragma unroll
            for (int nt = 0; nt < 8; nt++) {
                int col = nt * 8 + 2 * t;
                float2 lg = *(float2*)&l1gs[col];
                float2 lbb = *(float2*)&l1bs[col];
                hng[nt][0] = fmaxf((acc2[nt][0] - mu1g) * r1g * lg.x + lbb.x, 0.f);
                hng[nt][1] = fmaxf((acc2[nt][1] - mu1g) * r1g * lg.y + lbb.y, 0.f);
                hnh[nt][0] = fmaxf((acc2[nt][2] - mu1h) * r1h * lg.x + lbb.x, 0.f);
                hnh[nt][1] = fmaxf((acc2[nt][3] - mu1h) * r1h * lg.y + lbb.y, 0.f);
                xg[nt] = *(const float2*)&g_x1[(size_t)(r0 + g) * HH + col];
                xh[nt] = *(const float2*)&g_x1[(size_t)(r0 + g + 8) * HH + col];
                s2g += xg[nt].x + xg[nt].y + hng[nt][0] + hng[nt][1];
                q2g += xg[nt].x * xg[nt].x + xg[nt].y * xg[nt].y
                     + hng[nt][0] * hng[nt][0] + hng[nt][1] * hng[nt][1];
                s2h += xh[nt].x + xh[nt].y + hnh[nt][0] + hnh[nt][1];
                q2h += xh[nt].x * xh[nt].x + xh[nt].y * xh[nt].y
                     + hnh[nt][0] * hnh[nt][0] + hnh[nt][1] * hnh[nt][1];
            }
            s2g += __shfl_xor_sync(~0u, s2g, 1); s2g += __shfl_xor_sync(~0u, s2g, 2);
            q2g += __shfl_xor_sync(~0u, q2g, 1); q2g += __shfl_xor_sync(~0u, q2g, 2);
            s2h += __shfl_xor_sync(~0u, s2h, 1); s2h += __shfl_xor_sync(~0u, s2h, 2);
            q2h += __shfl_xor_sync(~0u, q2h, 1); q2h += __shfl_xor_sync(~0u, q2h, 2);
            float mu2g = s2g * (1.f / 128.f), mu2h = s2h * (1.f / 128.f);
            float r2g = rsqrtf(q2g * (1.f / 128.f) - mu2g * mu2g + 1e-5f);
            float r2h = rsqrtf(q2h * (1.f / 128.f) - mu2h * mu2h + 1e-5f);

            float dg = 0.f, dh = 0.f;
#pragma unroll
            for (int nt = 0; nt < 8; nt++) {
                int col = nt * 8 + 2 * t;
                float2 ngx = *(float2*)&ngs[col];
                float2 nbx = *(float2*)&nbs[col];
                float2 ngh2 = *(float2*)&ngs[64 + col];
                float2 nbh2 = *(float2*)&nbs[64 + col];
                float2 lwx = *(float2*)&lws[col];
                float2 lwh2 = *(float2*)&lws[64 + col];
                dg += fmaxf((xg[nt].x - mu2g) * r2g * ngx.x + nbx.x, 0.f) * lwx.x
                    + fmaxf((xg[nt].y - mu2g) * r2g * ngx.y + nbx.y, 0.f) * lwx.y
                    + fmaxf((hng[nt][0] - mu2g) * r2g * ngh2.x + nbh2.x, 0.f) * lwh2.x
                    + fmaxf((hng[nt][1] - mu2g) * r2g * ngh2.y + nbh2.y, 0.f) * lwh2.y;
                dh += fmaxf((xh[nt].x - mu2h) * r2h * ngx.x + nbx.x, 0.f) * lwx.x
                    + fmaxf((xh[nt].y - mu2h) * r2h * ngx.y + nbx.y, 0.f) * lwx.y
                    + fmaxf((hnh[nt][0] - mu2h) * r2h * ngh2.x + nbh2.x, 0.f) * lwh2.x
                    + fmaxf((hnh[nt][1] - mu2h) * r2h * ngh2.y + nbh2.y, 0.f) * lwh2.y;
            }
            dg += __shfl_xor_sync(~0u, dg, 1); dg += __shfl_xor_sync(~0u, dg, 2);
            dh += __shfl_xor_sync(~0u, dh, 1); dh += __shfl_xor_sync(~0u, dh, 2);
            if (t == 0) {
                out[r0 + g] = dg + lbv;
                out[r0 + g + 8] = dh + lbv;
            }
        }
    }

    PDL_TRIGGER();   // release agg2 (after mlp1's g_x1 writes)

    if (FINAL) {
        for (int i = blockIdx.x * blockDim.x + tid; i < NN; i += gridDim.x * blockDim.x)
            g_cnt[i] = 0;
        int i = blockIdx.x * blockDim.x + tid;
        if (i < SCAN_NBLK) *((unsigned long long*)&g_state[i]) = 0ULL;
    }
}

// ---------------- launch ----------------
extern "C" void kernel_launch(void* const* d_in, const int* in_sizes, int n_in,
                              void* d_out, int out_size) {
    const float* x    = (const float*)d_in[0];
    const void*  ei   = d_in[1];
    const float* encW = (const float*)d_in[2];
    const float* encB = (const float*)d_in[3];
    const float* t    = (const float*)d_in[4];
    const float* W1   = (const float*)d_in[5];
    const float* b1   = (const float*)d_in[6];
    const float* g1   = (const float*)d_in[7];
    const float* be1  = (const float*)d_in[8];
    const float* W2   = (const float*)d_in[9];
    const float* b2   = (const float*)d_in[10];
    const float* ln1g = (const float*)d_in[11];
    const float* ln1b = (const float*)d_in[12];
    const float* ng   = (const float*)d_in[13];
    const float* nb   = (const float*)d_in[14];
    const float* lw   = (const float*)d_in[15];
    const float* lb   = (const float*)d_in[16];
    float* out = (float*)d_out;

    const int AGG_BLOCKS = (NN * 32 + 255) / 256;

    cudaStream_t sB;
    cudaEvent_t evF, evJ;
    cudaStreamCreateWithFlags(&sB, cudaStreamNonBlocking);
    cudaEventCreateWithFlags(&evF, cudaEventDisableTiming);
    cudaEventCreateWithFlags(&evJ, cudaEventDisableTiming);

    // fork: encoder runs on sB, concurrent with the CSR chain
    cudaEventRecord(evF, 0);
    cudaStreamWaitEvent(sB, evF, 0);
    encoder_kernel<<<296, 128, 0, sB>>>(x, encW, encB);
    cudaEventRecord(evJ, sB);

    count_kernel<<<EDGE_BLOCKS, 256>>>((const int*)ei);
    scan_lb_kernel<<<SCAN_NBLK, 256>>>();
    scatter_kernel<<<EDGE_BLOCKS, 256>>>((const int*)ei);

    // join: agg1 needs both scatter (stream 0, via PDL) and encoder (sB)
    cudaStreamWaitEvent(0, evJ, 0);

    // PDL launch configs
    cudaLaunchAttribute pdlAttr[1];
    pdlAttr[0].id = cudaLaunchAttributeProgrammaticStreamSerialization;
    pdlAttr[0].val.programmaticStreamSerializationAllowed = 1;

    cudaLaunchConfig_t aggCfg = {};
    aggCfg.gridDim = dim3(AGG_BLOCKS, 1, 1);
    aggCfg.blockDim = dim3(256, 1, 1);
    aggCfg.attrs = pdlAttr;
    aggCfg.numAttrs = 1;
    aggCfg.stream = 0;

    cudaLaunchConfig_t mlpCfg = {};
    mlpCfg.gridDim = dim3(296, 1, 1);
    mlpCfg.blockDim = dim3(128, 1, 1);
    mlpCfg.attrs = pdlAttr;
    mlpCfg.numAttrs = 1;
    mlpCfg.stream = 0;

    cudaLaunchKernelEx(&aggCfg, agg_kernel, 0, t);
    cudaLaunchKernelEx(&mlpCfg, mlp_kernel<0>, W1, b1, g1, be1, W2, b2,
                       ln1g, ln1b, ng, nb, lw, lb, out);
    cudaLaunchKernelEx(&aggCfg, agg_kernel, 1, t);
    cudaLaunchKernelEx(&mlpCfg, mlp_kernel<1>, W1, b1, g1, be1, W2, b2,
                       ln1g, ln1b, ng, nb, lw, lb, out);
}